// round 3
// baseline (speedup 1.0000x reference)
#include <cuda_runtime.h>
#include <math.h>
#include <stdint.h>

#define Nn   65536
#define Bg   64
#define NPG  1024
#define Ag   32
#define HIDN 128
#define Eg   262144
#define Lg   3
#define NEG  0.2f

// ---------------- scratch (device globals; no allocation allowed) ----------------
__device__ float g_h[Nn * HIDN];
__device__ float g_xl[Nn * HIDN];
__device__ float g_xr[Nn * HIDN];
__device__ int   g_indptr[Nn + 1];
__device__ int   g_cursor[Nn];
__device__ int   g_deg[Nn];
__device__ int   g_csr_src[Eg];
__device__ float g_csr_ea[Eg];
__device__ float g_partial[1024];
__device__ float g_ea_mean;
__device__ float g_pool_sum[Bg * HIDN];
__device__ float g_pool_max[Bg * HIDN];

// ---------------- packed f32x2 helpers (sm_103a FFMA2) ----------------
__device__ __forceinline__ unsigned long long pack2(float lo, float hi) {
    unsigned long long r;
    asm("mov.b64 %0, {%1, %2};" : "=l"(r) : "f"(lo), "f"(hi));
    return r;
}
__device__ __forceinline__ void ffma2(unsigned long long& d, unsigned long long a, unsigned long long b) {
    asm("fma.rn.f32x2 %0, %1, %2, %0;" : "+l"(d) : "l"(a), "l"(b));
}
__device__ __forceinline__ float2 unpack2(unsigned long long v) {
    float2 f;
    asm("mov.b64 {%0, %1}, %2;" : "=f"(f.x), "=f"(f.y) : "l"(v));
    return f;
}

// ---------------- launch 1: zero counters ----------------
__global__ void k_zero() {
    int i = blockIdx.x * blockDim.x + threadIdx.x;
    if (i < Nn) g_deg[i] = 0;
    if (i < Bg * HIDN) { g_pool_sum[i] = 0.f; g_pool_max[i] = 0.f; }
}

// ---------------- launch 2: h0 = relu(x @ Wn + bn), NF = 1 ----------------
__global__ void k_inith(const float* __restrict__ x, const float* __restrict__ Wn,
                        const float* __restrict__ bn) {
    int idx = blockIdx.x * blockDim.x + threadIdx.x;   // Nn*32 threads
    int node = idx >> 5;
    int c = (idx & 31) << 2;
    float xv = x[node];
    float4 w = *(const float4*)(Wn + c);
    float4 b = *(const float4*)(bn + c);
    float4 o;
    o.x = fmaxf(fmaf(xv, w.x, b.x), 0.f);
    o.y = fmaxf(fmaf(xv, w.y, b.y), 0.f);
    o.z = fmaxf(fmaf(xv, w.z, b.z), 0.f);
    o.w = fmaxf(fmaf(xv, w.w, b.w), 0.f);
    *(float4*)(g_h + node * HIDN + c) = o;
}

// ---------------- launch 3: degree histogram + edge_attr mean partials ----------------
__global__ void k_hist(const int* __restrict__ ei, const float* __restrict__ ea) {
    __shared__ float red[256];
    int e = blockIdx.x * 256 + threadIdx.x;
    atomicAdd(&g_deg[ei[Eg + e]], 1);
    red[threadIdx.x] = ea[e];
    __syncthreads();
    for (int st = 128; st > 0; st >>= 1) {
        if (threadIdx.x < st) red[threadIdx.x] += red[threadIdx.x + st];
        __syncthreads();
    }
    if (threadIdx.x == 0) g_partial[blockIdx.x] = red[0];
}

// ---------------- launch 4: dual GEMM  xl = h@W1+b1, xr = h@W2+b2 ----------------
// tile: 128 rows x 256 cols, 512 threads, thread = 4 rows x 8 col-pairs (FFMA2)
// mainloop: 4 k per iteration, A via LDS.128, unrolled for SW pipelining
__global__ __launch_bounds__(512) void k_gemm_dual(const float* __restrict__ W1,
                                                   const float* __restrict__ W2,
                                                   const float* __restrict__ b1,
                                                   const float* __restrict__ b2) {
    extern __shared__ float sm[];
    float* sA = sm;               // 128 x 132 (pitch 132 floats = 528B, 16B aligned)
    float* sW = sm + 128 * 132;   // 128 x 256
    const int tid  = threadIdx.x;
    const int row0 = blockIdx.x * 128;

    for (int i = tid; i < 128 * 32; i += 512) {
        int r = i >> 5, c = (i & 31) << 2;
        *(float4*)(sA + r * 132 + c) = *(const float4*)(g_h + (size_t)(row0 + r) * HIDN + c);
        *(float4*)(sW + r * 256 + c)       = *(const float4*)(W1 + r * HIDN + c);
        *(float4*)(sW + r * 256 + 128 + c) = *(const float4*)(W2 + r * HIDN + c);
    }
    __syncthreads();

    const int tx = tid & 15, ty = tid >> 4;      // ty: 0..31 -> rows ty*4..ty*4+3
    unsigned long long acc[4][8];
    #pragma unroll
    for (int r = 0; r < 4; r++)
        #pragma unroll
        for (int p = 0; p < 8; p++) acc[r][p] = 0ull;

    const float* pA = sA + ty * 4 * 132;
    const float* pW = sW + tx * 2;               // pair columns: c = tx*2 + p*32

    #pragma unroll 2
    for (int k4 = 0; k4 < 128; k4 += 4) {
        float4 a4[4];
        #pragma unroll
        for (int r = 0; r < 4; r++) a4[r] = *(const float4*)(pA + r * 132 + k4);

        #pragma unroll
        for (int kk = 0; kk < 4; kk++) {
            unsigned long long wv[8];
            #pragma unroll
            for (int p = 0; p < 8; p++)
                wv[p] = *(const unsigned long long*)(pW + (size_t)(k4 + kk) * 256 + p * 32);
            #pragma unroll
            for (int r = 0; r < 4; r++) {
                float a = (kk == 0) ? a4[r].x : (kk == 1) ? a4[r].y : (kk == 2) ? a4[r].z : a4[r].w;
                unsigned long long av = pack2(a, a);
                #pragma unroll
                for (int p = 0; p < 8; p++) ffma2(acc[r][p], av, wv[p]);
            }
        }
    }

    #pragma unroll
    for (int p = 0; p < 8; p++) {
        int c = tx * 2 + p * 32;                 // 0..254
        const float* bb = (c < 128) ? b1 : b2;
        float* outp     = (c < 128) ? g_xl : g_xr;
        int cc = c & 127;
        float2 bv = *(const float2*)(bb + cc);
        #pragma unroll
        for (int r = 0; r < 4; r++) {
            float2 v = unpack2(acc[r][p]);
            v.x += bv.x; v.y += bv.y;
            *(float2*)(outp + (size_t)(row0 + ty * 4 + r) * HIDN + cc) = v;
        }
    }
}

// ---------------- launch 5: exclusive scan of degrees + finish edge_attr mean ----------------
__global__ __launch_bounds__(1024) void k_scan() {
    __shared__ int   ssum[1024];
    __shared__ float fred[1024];
    int t = threadIdx.x;

    fred[t] = g_partial[t];
    int base = t * 64;
    int s = 0;
    #pragma unroll 8
    for (int i = 0; i < 64; i++) s += g_deg[base + i];
    ssum[t] = s; __syncthreads();
    for (int off = 1; off < 1024; off <<= 1) {
        int v = (t >= off) ? ssum[t - off] : 0;
        __syncthreads();
        ssum[t] += v;
        __syncthreads();
    }
    int run = (t == 0) ? 0 : ssum[t - 1];
    for (int i = 0; i < 64; i++) {
        g_indptr[base + i] = run;
        g_cursor[base + i] = run;
        run += g_deg[base + i];
    }
    if (t == 1023) g_indptr[Nn] = run;

    for (int st = 512; st > 0; st >>= 1) {
        __syncthreads();
        if (t < st) fred[t] += fred[t + st];
    }
    __syncthreads();
    if (t == 0) g_ea_mean = fred[0] / (float)Eg;
}

// ---------------- launch 6: CSR fill ----------------
__global__ void k_fill(const int* __restrict__ ei, const float* __restrict__ ea) {
    int e = blockIdx.x * blockDim.x + threadIdx.x;
    if (e < Eg) {
        int d = ei[Eg + e];
        int pos = atomicAdd(&g_cursor[d], 1);
        g_csr_src[pos] = ei[e];
        g_csr_ea[pos]  = ea[e];
    }
}

// ---------------- edge aggregation: one warp per node, online softmax, unroll-4 ----------------
__global__ __launch_bounds__(256) void k_edge(const float* __restrict__ We,
                                              const float* __restrict__ att,
                                              const float* __restrict__ gb) {
    int warp = (blockIdx.x * blockDim.x + threadIdx.x) >> 5;
    int lane = threadIdx.x & 31;
    if (warp >= Nn) return;
    const int i = warp;

    float wv[4], av[4], xr_[4], xls[4], hold[4];
    #pragma unroll
    for (int r = 0; r < 4; r++) {
        int j = r * 32 + lane;
        wv[r]   = We[j];
        av[r]   = att[j];
        xr_[r]  = g_xr[(size_t)i * HIDN + j];
        xls[r]  = g_xl[(size_t)i * HIDN + j];
        hold[r] = g_h[(size_t)i * HIDN + j];
    }
    float eam = g_ea_mean;

    // self-loop initializes online softmax state
    float m[4], s[4], acc[4];
    {
        float p[4];
        #pragma unroll
        for (int r = 0; r < 4; r++) {
            float t = fmaf(eam, wv[r], xls[r] + xr_[r]);
            t = (t > 0.f) ? t : NEG * t;
            p[r] = t * av[r];
        }
        #pragma unroll
        for (int o = 16; o > 0; o >>= 1) {
            #pragma unroll
            for (int r = 0; r < 4; r++) p[r] += __shfl_xor_sync(0xffffffffu, p[r], o);
        }
        #pragma unroll
        for (int r = 0; r < 4; r++) { m[r] = p[r]; s[r] = 1.f; acc[r] = xls[r]; }
    }

    int e0 = g_indptr[i], e1 = g_indptr[i + 1];
    int e = e0;

    for (; e + 4 <= e1; e += 4) {
        int   src[4];
        float a[4];
        #pragma unroll
        for (int u = 0; u < 4; u++) { src[u] = g_csr_src[e + u]; a[u] = g_csr_ea[e + u]; }

        float xs[4][4], q[4][4];
        #pragma unroll
        for (int u = 0; u < 4; u++)
            #pragma unroll
            for (int r = 0; r < 4; r++)
                xs[u][r] = __ldg(&g_xl[(size_t)src[u] * HIDN + r * 32 + lane]);

        #pragma unroll
        for (int u = 0; u < 4; u++)
            #pragma unroll
            for (int r = 0; r < 4; r++) {
                float t = fmaf(a[u], wv[r], xs[u][r] + xr_[r]);
                t = (t > 0.f) ? t : NEG * t;
                q[u][r] = t * av[r];
            }

        // 16 independent butterfly chains, fully interleaved
        #pragma unroll
        for (int o = 16; o > 0; o >>= 1)
            #pragma unroll
            for (int u = 0; u < 4; u++)
                #pragma unroll
                for (int r = 0; r < 4; r++)
                    q[u][r] += __shfl_xor_sync(0xffffffffu, q[u][r], o);

        #pragma unroll
        for (int r = 0; r < 4; r++) {
            float mx01 = fmaxf(q[0][r], q[1][r]);
            float mx23 = fmaxf(q[2][r], q[3][r]);
            float mn = fmaxf(m[r], fmaxf(mx01, mx23));
            float sc = __expf(m[r] - mn);
            float p0 = __expf(q[0][r] - mn);
            float p1 = __expf(q[1][r] - mn);
            float p2 = __expf(q[2][r] - mn);
            float p3 = __expf(q[3][r] - mn);
            s[r]   = fmaf(s[r], sc, (p0 + p1) + (p2 + p3));
            float w01 = fmaf(p0, xs[0][r], p1 * xs[1][r]);
            float w23 = fmaf(p2, xs[2][r], p3 * xs[3][r]);
            acc[r] = fmaf(acc[r], sc, w01 + w23);
            m[r]   = mn;
        }
    }

    for (; e < e1; e++) {
        int   src = g_csr_src[e];
        float a   = g_csr_ea[e];
        float xs[4], q[4];
        #pragma unroll
        for (int r = 0; r < 4; r++) {
            xs[r] = __ldg(&g_xl[(size_t)src * HIDN + r * 32 + lane]);
            float t = fmaf(a, wv[r], xs[r] + xr_[r]);
            t = (t > 0.f) ? t : NEG * t;
            q[r] = t * av[r];
        }
        #pragma unroll
        for (int o = 16; o > 0; o >>= 1) {
            #pragma unroll
            for (int r = 0; r < 4; r++) q[r] += __shfl_xor_sync(0xffffffffu, q[r], o);
        }
        #pragma unroll
        for (int r = 0; r < 4; r++) {
            float mn = fmaxf(m[r], q[r]);
            float sc = __expf(m[r] - mn);
            float p  = __expf(q[r] - mn);
            s[r]   = fmaf(s[r], sc, p);
            acc[r] = fmaf(acc[r], sc, p * xs[r]);
            m[r]   = mn;
        }
    }

    #pragma unroll
    for (int r = 0; r < 4; r++) {
        float o = acc[r] / s[r] + gb[r * 32 + lane];
        g_h[(size_t)i * HIDN + r * 32 + lane] = fmaxf(o, 0.f) + hold[r];
    }
}

// ---------------- pooling (h >= 0, so int-bit atomicMax is valid) ----------------
__global__ void k_pool() {
    int b = blockIdx.x >> 3;
    int chunk = blockIdx.x & 7;
    int j = threadIdx.x;
    int node0 = b * NPG + chunk * 128;
    float s = 0.f, mx = 0.f;
    #pragma unroll 4
    for (int t = 0; t < 128; t++) {
        float v = g_h[(size_t)(node0 + t) * HIDN + j];
        s += v;
        mx = fmaxf(mx, v);
    }
    atomicAdd(&g_pool_sum[b * HIDN + j], s);
    atomicMax((int*)&g_pool_max[b * HIDN + j], __float_as_int(mx));
}

// ---------------- fused action encoder + Q head ----------------
__global__ __launch_bounds__(256) void k_head(const float* __restrict__ at,
        const float* __restrict__ aW1, const float* __restrict__ ab1,
        const float* __restrict__ aW2, const float* __restrict__ ab2,
        const float* __restrict__ qW1, const float* __restrict__ qb1,
        const float* __restrict__ qW2, const float* __restrict__ qb2,
        const float* __restrict__ qW3, const float* __restrict__ qb3,
        float* __restrict__ out) {
    extern __shared__ float sm[];
    float* IN   = sm;                 // 16 x 516
    float* S1   = IN + 16 * 516;      // 16 x 128
    float* S2   = S1 + 16 * 128;      // 16 x 128
    float* tcol = S2 + 16 * 128;      // 128
    float* ps   = tcol + 128;         // 128
    float* pm   = ps + 128;           // 128

    const int tid = threadIdx.x;
    const int b   = blockIdx.x >> 1;
    const int a0  = (blockIdx.x & 1) * 16;

    if (tid < 128) {
        ps[tid] = g_pool_sum[b * HIDN + tid];
        pm[tid] = g_pool_max[b * HIDN + tid];
    }
    __syncthreads();

    for (int idx = tid; idx < 16 * 512; idx += 256) {
        int a = idx >> 9, q = idx & 511;
        int slot = q >> 7, col = q & 127;
        int node = (int)at[(size_t)(b * Ag + a0 + a) * 7 + slot] + b * NPG;
        IN[a * 516 + q] = g_h[(size_t)node * HIDN + col];
    }
    for (int idx = tid; idx < 16 * 3; idx += 256) {
        int a = idx / 3, ms = idx % 3;
        IN[a * 516 + 512 + ms] = at[(size_t)(b * Ag + a0 + a) * 7 + 4 + ms];
    }
    if (tid < 128) {
        float acc = qb1[tid];
        for (int k = 0; k < 128; k++) {
            float sv = ps[k];
            acc = fmaf(sv, qW1[k * 128 + tid], acc);
            acc = fmaf(sv * (1.f / 1024.f), qW1[(128 + k) * 128 + tid], acc);
            acc = fmaf(pm[k], qW1[(256 + k) * 128 + tid], acc);
        }
        tcol[tid] = acc;
    }
    __syncthreads();

    const int col = tid & 127;
    const int ab  = (tid >> 7) * 8;

    {
        float acc[8]; float bias = ab1[col];
        #pragma unroll
        for (int a = 0; a < 8; a++) acc[a] = bias;
        for (int k = 0; k < 515; k++) {
            float w = aW1[k * 128 + col];
            #pragma unroll
            for (int a = 0; a < 8; a++) acc[a] = fmaf(IN[(ab + a) * 516 + k], w, acc[a]);
        }
        #pragma unroll
        for (int a = 0; a < 8; a++) S1[(ab + a) * 128 + col] = fmaxf(acc[a], 0.f);
    }
    __syncthreads();
    {
        float acc[8]; float bias = ab2[col];
        #pragma unroll
        for (int a = 0; a < 8; a++) acc[a] = bias;
        for (int k = 0; k < 128; k++) {
            float w = aW2[k * 128 + col];
            #pragma unroll
            for (int a = 0; a < 8; a++) acc[a] = fmaf(S1[(ab + a) * 128 + k], w, acc[a]);
        }
        #pragma unroll
        for (int a = 0; a < 8; a++) S2[(ab + a) * 128 + col] = fmaxf(acc[a], 0.f);
    }
    __syncthreads();
    {
        float acc[8]; float t = tcol[col];
        #pragma unroll
        for (int a = 0; a < 8; a++) acc[a] = t;
        for (int k = 0; k < 128; k++) {
            float w = qW1[(384 + k) * 128 + col];
            #pragma unroll
            for (int a = 0; a < 8; a++) acc[a] = fmaf(S2[(ab + a) * 128 + k], w, acc[a]);
        }
        #pragma unroll
        for (int a = 0; a < 8; a++) S1[(ab + a) * 128 + col] = fmaxf(acc[a], 0.f);
    }
    __syncthreads();
    {
        float acc[8]; float bias = qb2[col];
        #pragma unroll
        for (int a = 0; a < 8; a++) acc[a] = bias;
        for (int k = 0; k < 128; k++) {
            float w = qW2[k * 128 + col];
            #pragma unroll
            for (int a = 0; a < 8; a++) acc[a] = fmaf(S1[(ab + a) * 128 + k], w, acc[a]);
        }
        #pragma unroll
        for (int a = 0; a < 8; a++) S2[(ab + a) * 128 + col] = fmaxf(acc[a], 0.f);
    }
    __syncthreads();
    {
        int w_id = tid >> 5, lane = tid & 31;
        for (int a = w_id; a < 16; a += 8) {
            float s = 0.f;
            #pragma unroll
            for (int kk = 0; kk < 4; kk++)
                s = fmaf(S2[a * 128 + kk * 32 + lane], qW3[kk * 32 + lane], s);
            #pragma unroll
            for (int o = 16; o > 0; o >>= 1) s += __shfl_xor_sync(0xffffffffu, s, o);
            if (lane == 0) out[b * Ag + a0 + a] = s + qb3[0];
        }
    }
}

// ---------------- launch ----------------
extern "C" void kernel_launch(void* const* d_in, const int* in_sizes, int n_in,
                              void* d_out, int out_size) {
    const float *x, *edge_attr, *action_tensor;
    const float *Wn, *bn, *gWl, *gbl, *gWr, *gbr, *gWe, *gatt, *gb;
    const float *aW1, *ab1, *aW2, *ab2, *qW1, *qb1, *qW2, *qb2, *qW3, *qb3;
    const int* edge_index;

    x             = (const float*)d_in[0];
    edge_attr     = (const float*)d_in[1];
    action_tensor = (const float*)d_in[2];

    if (in_sizes[3] > 100000) {
        edge_index = (const int*)d_in[3];
        Wn  = (const float*)d_in[6];  bn  = (const float*)d_in[7];
        gWl = (const float*)d_in[8];  gWr = (const float*)d_in[9];
        gWe = (const float*)d_in[10]; gatt= (const float*)d_in[11];
        gbl = (const float*)d_in[12]; gbr = (const float*)d_in[13];
        gb  = (const float*)d_in[14];
        aW1 = (const float*)d_in[15]; ab1 = (const float*)d_in[16];
        aW2 = (const float*)d_in[17]; ab2 = (const float*)d_in[18];
        qW1 = (const float*)d_in[19]; qb1 = (const float*)d_in[20];
        qW2 = (const float*)d_in[21]; qb2 = (const float*)d_in[22];
        qW3 = (const float*)d_in[23]; qb3 = (const float*)d_in[24];
    } else {
        Wn  = (const float*)d_in[3];  bn  = (const float*)d_in[4];
        gWl = (const float*)d_in[5];  gbl = (const float*)d_in[6];
        gWr = (const float*)d_in[7];  gbr = (const float*)d_in[8];
        gWe = (const float*)d_in[9];  gatt= (const float*)d_in[10];
        gb  = (const float*)d_in[11];
        aW1 = (const float*)d_in[12]; ab1 = (const float*)d_in[13];
        aW2 = (const float*)d_in[14]; ab2 = (const float*)d_in[15];
        qW1 = (const float*)d_in[16]; qb1 = (const float*)d_in[17];
        qW2 = (const float*)d_in[18]; qb2 = (const float*)d_in[19];
        qW3 = (const float*)d_in[20]; qb3 = (const float*)d_in[21];
        edge_index = (const int*)d_in[22];
    }

    const int SMEM_G = (128 * 132 + 128 * 256) * 4;                   // 198656
    const int SMEM_H = (16 * 516 + 2 * 16 * 128 + 3 * 128) * 4;       // 50944
    cudaFuncSetAttribute(k_gemm_dual, cudaFuncAttributeMaxDynamicSharedMemorySize, SMEM_G);
    cudaFuncSetAttribute(k_head,      cudaFuncAttributeMaxDynamicSharedMemorySize, SMEM_H);

    k_zero<<<Nn / 256, 256>>>();                                   // 1
    k_inith<<<Nn * 32 / 256, 256>>>(x, Wn, bn);                    // 2
    k_hist<<<Eg / 256, 256>>>(edge_index, edge_attr);              // 3
    k_gemm_dual<<<Nn / 128, 512, SMEM_G>>>(gWl, gWr, gbl, gbr);    // 4  <- ncu capture target
    k_scan<<<1, 1024>>>();                                         // 5
    k_fill<<<Eg / 256, 256>>>(edge_index, edge_attr);              // 6
    k_edge<<<Nn / 8, 256>>>(gWe, gatt, gb);                        // 7

    for (int l = 1; l < Lg; l++) {
        k_gemm_dual<<<Nn / 128, 512, SMEM_G>>>(gWl + l * HIDN * HIDN, gWr + l * HIDN * HIDN,
                                               gbl + l * HIDN, gbr + l * HIDN);
        k_edge<<<Nn / 8, 256>>>(gWe + l * HIDN, gatt + l * HIDN, gb + l * HIDN);
    }

    k_pool<<<Bg * 8, 128>>>();
    k_head<<<Bg * 2, 256, SMEM_H>>>(action_tensor, aW1, ab1, aW2, ab2,
                                    qW1, qb1, qW2, qb2, qW3, qb3, (float*)d_out);
}

// round 4
// speedup vs baseline: 1.0149x; 1.0149x over previous
#include <cuda_runtime.h>
#include <math.h>
#include <stdint.h>

#define Nn   65536
#define Bg   64
#define NPG  1024
#define Ag   32
#define HIDN 128
#define Eg   262144
#define Lg   3
#define NEG  0.2f

// ---------------- scratch (device globals; no allocation allowed) ----------------
__device__ float g_h[Nn * HIDN];
__device__ float g_xl[Nn * HIDN];
__device__ float g_xr[Nn * HIDN];
__device__ int   g_indptr[Nn + 1];
__device__ int   g_cursor[Nn];
__device__ int   g_deg[Nn];
__device__ int   g_csr_src[Eg];
__device__ int   g_csr_dst[Eg];
__device__ float g_csr_ea[Eg];
__device__ float4 g_logit[Eg];
__device__ float4 g_logit_self[Nn];
__device__ float g_partial[1024];
__device__ float g_ea_mean;
__device__ float g_pool_sum[Bg * HIDN];
__device__ float g_pool_max[Bg * HIDN];

// ---------------- packed f32x2 helpers (sm_103a FFMA2) ----------------
__device__ __forceinline__ unsigned long long pack2(float lo, float hi) {
    unsigned long long r;
    asm("mov.b64 %0, {%1, %2};" : "=l"(r) : "f"(lo), "f"(hi));
    return r;
}
__device__ __forceinline__ void ffma2(unsigned long long& d, unsigned long long a, unsigned long long b) {
    asm("fma.rn.f32x2 %0, %1, %2, %0;" : "+l"(d) : "l"(a), "l"(b));
}
__device__ __forceinline__ float2 unpack2(unsigned long long v) {
    float2 f;
    asm("mov.b64 {%0, %1}, %2;" : "=f"(f.x), "=f"(f.y) : "l"(v));
    return f;
}

// ---------------- launch 1: zero counters ----------------
__global__ void k_zero() {
    int i = blockIdx.x * blockDim.x + threadIdx.x;
    if (i < Nn) g_deg[i] = 0;
    if (i < Bg * HIDN) { g_pool_sum[i] = 0.f; g_pool_max[i] = 0.f; }
}

// ---------------- launch 2: h0 = relu(x @ Wn + bn), NF = 1 ----------------
__global__ void k_inith(const float* __restrict__ x, const float* __restrict__ Wn,
                        const float* __restrict__ bn) {
    int idx = blockIdx.x * blockDim.x + threadIdx.x;
    int node = idx >> 5;
    int c = (idx & 31) << 2;
    float xv = x[node];
    float4 w = *(const float4*)(Wn + c);
    float4 b = *(const float4*)(bn + c);
    float4 o;
    o.x = fmaxf(fmaf(xv, w.x, b.x), 0.f);
    o.y = fmaxf(fmaf(xv, w.y, b.y), 0.f);
    o.z = fmaxf(fmaf(xv, w.z, b.z), 0.f);
    o.w = fmaxf(fmaf(xv, w.w, b.w), 0.f);
    *(float4*)(g_h + node * HIDN + c) = o;
}

// ---------------- launch 3: degree histogram + edge_attr mean partials ----------------
__global__ void k_hist(const int* __restrict__ ei, const float* __restrict__ ea) {
    __shared__ float red[256];
    int e = blockIdx.x * 256 + threadIdx.x;
    atomicAdd(&g_deg[ei[Eg + e]], 1);
    red[threadIdx.x] = ea[e];
    __syncthreads();
    for (int st = 128; st > 0; st >>= 1) {
        if (threadIdx.x < st) red[threadIdx.x] += red[threadIdx.x + st];
        __syncthreads();
    }
    if (threadIdx.x == 0) g_partial[blockIdx.x] = red[0];
}

// ---------------- launch 4: dual GEMM  xl = h@W1+b1, xr = h@W2+b2 ----------------
__global__ __launch_bounds__(512) void k_gemm_dual(const float* __restrict__ W1,
                                                   const float* __restrict__ W2,
                                                   const float* __restrict__ b1,
                                                   const float* __restrict__ b2) {
    extern __shared__ float sm[];
    float* sA = sm;               // 128 x 132
    float* sW = sm + 128 * 132;   // 128 x 256
    const int tid  = threadIdx.x;
    const int row0 = blockIdx.x * 128;

    for (int i = tid; i < 128 * 32; i += 512) {
        int r = i >> 5, c = (i & 31) << 2;
        *(float4*)(sA + r * 132 + c) = *(const float4*)(g_h + (size_t)(row0 + r) * HIDN + c);
        *(float4*)(sW + r * 256 + c)       = *(const float4*)(W1 + r * HIDN + c);
        *(float4*)(sW + r * 256 + 128 + c) = *(const float4*)(W2 + r * HIDN + c);
    }
    __syncthreads();

    const int tx = tid & 15, ty = tid >> 4;
    unsigned long long acc[4][8];
    #pragma unroll
    for (int r = 0; r < 4; r++)
        #pragma unroll
        for (int p = 0; p < 8; p++) acc[r][p] = 0ull;

    const float* pA = sA + ty * 4 * 132;
    const float* pW = sW + tx * 2;

    #pragma unroll 2
    for (int k4 = 0; k4 < 128; k4 += 4) {
        float4 a4[4];
        #pragma unroll
        for (int r = 0; r < 4; r++) a4[r] = *(const float4*)(pA + r * 132 + k4);

        #pragma unroll
        for (int kk = 0; kk < 4; kk++) {
            unsigned long long wv[8];
            #pragma unroll
            for (int p = 0; p < 8; p++)
                wv[p] = *(const unsigned long long*)(pW + (size_t)(k4 + kk) * 256 + p * 32);
            #pragma unroll
            for (int r = 0; r < 4; r++) {
                float a = (kk == 0) ? a4[r].x : (kk == 1) ? a4[r].y : (kk == 2) ? a4[r].z : a4[r].w;
                unsigned long long av = pack2(a, a);
                #pragma unroll
                for (int p = 0; p < 8; p++) ffma2(acc[r][p], av, wv[p]);
            }
        }
    }

    #pragma unroll
    for (int p = 0; p < 8; p++) {
        int c = tx * 2 + p * 32;
        const float* bb = (c < 128) ? b1 : b2;
        float* outp     = (c < 128) ? g_xl : g_xr;
        int cc = c & 127;
        float2 bv = *(const float2*)(bb + cc);
        #pragma unroll
        for (int r = 0; r < 4; r++) {
            float2 v = unpack2(acc[r][p]);
            v.x += bv.x; v.y += bv.y;
            *(float2*)(outp + (size_t)(row0 + ty * 4 + r) * HIDN + cc) = v;
        }
    }
}

// ---------------- launch 5: exclusive scan of degrees + finish edge_attr mean ----------------
__global__ __launch_bounds__(1024) void k_scan() {
    __shared__ int   ssum[1024];
    __shared__ float fred[1024];
    int t = threadIdx.x;

    fred[t] = g_partial[t];
    int base = t * 64;
    int s = 0;
    #pragma unroll 8
    for (int i = 0; i < 64; i++) s += g_deg[base + i];
    ssum[t] = s; __syncthreads();
    for (int off = 1; off < 1024; off <<= 1) {
        int v = (t >= off) ? ssum[t - off] : 0;
        __syncthreads();
        ssum[t] += v;
        __syncthreads();
    }
    int run = (t == 0) ? 0 : ssum[t - 1];
    for (int i = 0; i < 64; i++) {
        g_indptr[base + i] = run;
        g_cursor[base + i] = run;
        run += g_deg[base + i];
    }
    if (t == 1023) g_indptr[Nn] = run;

    for (int st = 512; st > 0; st >>= 1) {
        __syncthreads();
        if (t < st) fred[t] += fred[t + st];
    }
    __syncthreads();
    if (t == 0) g_ea_mean = fred[0] / (float)Eg;
}

// ---------------- launch 6: CSR fill (stores src, dst, ea) ----------------
__global__ void k_fill(const int* __restrict__ ei, const float* __restrict__ ea) {
    int e = blockIdx.x * blockDim.x + threadIdx.x;
    if (e < Eg) {
        int d = ei[Eg + e];
        int pos = atomicAdd(&g_cursor[d], 1);
        g_csr_src[pos] = ei[e];
        g_csr_dst[pos] = d;
        g_csr_ea[pos]  = ea[e];
    }
}

// ---------------- phase 1: per-edge logits — one warp per edge, no loops ----------------
__global__ __launch_bounds__(256) void k_logit(const float* __restrict__ We,
                                               const float* __restrict__ att) {
    int idx  = (blockIdx.x * blockDim.x + threadIdx.x) >> 5;   // edge slot or self
    int lane = threadIdx.x & 31;
    if (idx >= Eg + Nn) return;

    int src, dst;
    float a;
    if (idx < Eg) {
        src = g_csr_src[idx];
        dst = g_csr_dst[idx];
        a   = g_csr_ea[idx];
    } else {
        src = dst = idx - Eg;
        a   = g_ea_mean;
    }

    float q[4];
    #pragma unroll
    for (int r = 0; r < 4; r++) {
        int j = r * 32 + lane;
        float v = __ldg(&g_xl[(size_t)src * HIDN + j]) + __ldg(&g_xr[(size_t)dst * HIDN + j]);
        v = fmaf(a, __ldg(&We[j]), v);
        v = (v > 0.f) ? v : NEG * v;
        q[r] = v * __ldg(&att[j]);
    }
    #pragma unroll
    for (int o = 16; o > 0; o >>= 1) {
        #pragma unroll
        for (int r = 0; r < 4; r++) q[r] += __shfl_xor_sync(0xffffffffu, q[r], o);
    }
    if (lane == 0) {
        float4 v = make_float4(q[0], q[1], q[2], q[3]);
        if (idx < Eg) g_logit[idx] = v;
        else          g_logit_self[idx - Eg] = v;
    }
}

// ---------------- phase 2: per-node softmax + weighted gather-sum (no shuffles) ----------------
__global__ __launch_bounds__(256) void k_aggr(const float* __restrict__ gb) {
    int i    = (blockIdx.x * blockDim.x + threadIdx.x) >> 5;
    int lane = threadIdx.x & 31;
    if (i >= Nn) return;

    float xls[4], hold[4];
    #pragma unroll
    for (int r = 0; r < 4; r++) {
        int j = r * 32 + lane;
        xls[r]  = g_xl[(size_t)i * HIDN + j];
        hold[r] = g_h[(size_t)i * HIDN + j];
    }

    const int e0 = g_indptr[i], e1 = g_indptr[i + 1];

    // pass 1: max over logits (broadcast float4 reads, all lanes identical)
    float4 lsf = g_logit_self[i];
    float m[4] = {lsf.x, lsf.y, lsf.z, lsf.w};
    for (int e = e0; e < e1; e++) {
        float4 lg = __ldg(&g_logit[e]);
        m[0] = fmaxf(m[0], lg.x);
        m[1] = fmaxf(m[1], lg.y);
        m[2] = fmaxf(m[2], lg.z);
        m[3] = fmaxf(m[3], lg.w);
    }

    // pass 2: exp-weights + weighted sum of xl[src]
    float s[4], acc[4];
    {
        float p0 = __expf(lsf.x - m[0]);
        float p1 = __expf(lsf.y - m[1]);
        float p2 = __expf(lsf.z - m[2]);
        float p3 = __expf(lsf.w - m[3]);
        s[0] = p0; s[1] = p1; s[2] = p2; s[3] = p3;
        acc[0] = p0 * xls[0]; acc[1] = p1 * xls[1];
        acc[2] = p2 * xls[2]; acc[3] = p3 * xls[3];
    }
    #pragma unroll 2
    for (int e = e0; e < e1; e++) {
        float4 lg = __ldg(&g_logit[e]);
        int src   = g_csr_src[e];
        float p[4];
        p[0] = __expf(lg.x - m[0]);
        p[1] = __expf(lg.y - m[1]);
        p[2] = __expf(lg.z - m[2]);
        p[3] = __expf(lg.w - m[3]);
        #pragma unroll
        for (int r = 0; r < 4; r++) {
            float xs = __ldg(&g_xl[(size_t)src * HIDN + r * 32 + lane]);
            s[r]   += 0.f;  // s update below keeps dependency short
            acc[r]  = fmaf(p[r], xs, acc[r]);
        }
        s[0] += p[0]; s[1] += p[1]; s[2] += p[2]; s[3] += p[3];
    }

    #pragma unroll
    for (int r = 0; r < 4; r++) {
        float o = acc[r] / s[r] + __ldg(&gb[r * 32 + lane]);
        g_h[(size_t)i * HIDN + r * 32 + lane] = fmaxf(o, 0.f) + hold[r];
    }
}

// ---------------- pooling ----------------
__global__ void k_pool() {
    int b = blockIdx.x >> 3;
    int chunk = blockIdx.x & 7;
    int j = threadIdx.x;
    int node0 = b * NPG + chunk * 128;
    float s = 0.f, mx = 0.f;
    #pragma unroll 4
    for (int t = 0; t < 128; t++) {
        float v = g_h[(size_t)(node0 + t) * HIDN + j];
        s += v;
        mx = fmaxf(mx, v);
    }
    atomicAdd(&g_pool_sum[b * HIDN + j], s);
    atomicMax((int*)&g_pool_max[b * HIDN + j], __float_as_int(mx));
}

// ---------------- fused action encoder + Q head ----------------
__global__ __launch_bounds__(256) void k_head(const float* __restrict__ at,
        const float* __restrict__ aW1, const float* __restrict__ ab1,
        const float* __restrict__ aW2, const float* __restrict__ ab2,
        const float* __restrict__ qW1, const float* __restrict__ qb1,
        const float* __restrict__ qW2, const float* __restrict__ qb2,
        const float* __restrict__ qW3, const float* __restrict__ qb3,
        float* __restrict__ out) {
    extern __shared__ float sm[];
    float* IN   = sm;                 // 16 x 516
    float* S1   = IN + 16 * 516;      // 16 x 128
    float* S2   = S1 + 16 * 128;      // 16 x 128
    float* tcol = S2 + 16 * 128;      // 128
    float* ps   = tcol + 128;         // 128
    float* pm   = ps + 128;           // 128

    const int tid = threadIdx.x;
    const int b   = blockIdx.x >> 1;
    const int a0  = (blockIdx.x & 1) * 16;

    if (tid < 128) {
        ps[tid] = g_pool_sum[b * HIDN + tid];
        pm[tid] = g_pool_max[b * HIDN + tid];
    }
    __syncthreads();

    for (int idx = tid; idx < 16 * 512; idx += 256) {
        int a = idx >> 9, q = idx & 511;
        int slot = q >> 7, col = q & 127;
        int node = (int)at[(size_t)(b * Ag + a0 + a) * 7 + slot] + b * NPG;
        IN[a * 516 + q] = g_h[(size_t)node * HIDN + col];
    }
    for (int idx = tid; idx < 16 * 3; idx += 256) {
        int a = idx / 3, ms = idx % 3;
        IN[a * 516 + 512 + ms] = at[(size_t)(b * Ag + a0 + a) * 7 + 4 + ms];
    }
    if (tid < 128) {
        float acc = qb1[tid];
        for (int k = 0; k < 128; k++) {
            float sv = ps[k];
            acc = fmaf(sv, qW1[k * 128 + tid], acc);
            acc = fmaf(sv * (1.f / 1024.f), qW1[(128 + k) * 128 + tid], acc);
            acc = fmaf(pm[k], qW1[(256 + k) * 128 + tid], acc);
        }
        tcol[tid] = acc;
    }
    __syncthreads();

    const int col = tid & 127;
    const int ab  = (tid >> 7) * 8;

    {
        float acc[8]; float bias = ab1[col];
        #pragma unroll
        for (int a = 0; a < 8; a++) acc[a] = bias;
        for (int k = 0; k < 515; k++) {
            float w = aW1[k * 128 + col];
            #pragma unroll
            for (int a = 0; a < 8; a++) acc[a] = fmaf(IN[(ab + a) * 516 + k], w, acc[a]);
        }
        #pragma unroll
        for (int a = 0; a < 8; a++) S1[(ab + a) * 128 + col] = fmaxf(acc[a], 0.f);
    }
    __syncthreads();
    {
        float acc[8]; float bias = ab2[col];
        #pragma unroll
        for (int a = 0; a < 8; a++) acc[a] = bias;
        for (int k = 0; k < 128; k++) {
            float w = aW2[k * 128 + col];
            #pragma unroll
            for (int a = 0; a < 8; a++) acc[a] = fmaf(S1[(ab + a) * 128 + k], w, acc[a]);
        }
        #pragma unroll
        for (int a = 0; a < 8; a++) S2[(ab + a) * 128 + col] = fmaxf(acc[a], 0.f);
    }
    __syncthreads();
    {
        float acc[8]; float t = tcol[col];
        #pragma unroll
        for (int a = 0; a < 8; a++) acc[a] = t;
        for (int k = 0; k < 128; k++) {
            float w = qW1[(384 + k) * 128 + col];
            #pragma unroll
            for (int a = 0; a < 8; a++) acc[a] = fmaf(S2[(ab + a) * 128 + k], w, acc[a]);
        }
        #pragma unroll
        for (int a = 0; a < 8; a++) S1[(ab + a) * 128 + col] = fmaxf(acc[a], 0.f);
    }
    __syncthreads();
    {
        float acc[8]; float bias = qb2[col];
        #pragma unroll
        for (int a = 0; a < 8; a++) acc[a] = bias;
        for (int k = 0; k < 128; k++) {
            float w = qW2[k * 128 + col];
            #pragma unroll
            for (int a = 0; a < 8; a++) acc[a] = fmaf(S1[(ab + a) * 128 + k], w, acc[a]);
        }
        #pragma unroll
        for (int a = 0; a < 8; a++) S2[(ab + a) * 128 + col] = fmaxf(acc[a], 0.f);
    }
    __syncthreads();
    {
        int w_id = tid >> 5, lane = tid & 31;
        for (int a = w_id; a < 16; a += 8) {
            float s = 0.f;
            #pragma unroll
            for (int kk = 0; kk < 4; kk++)
                s = fmaf(S2[a * 128 + kk * 32 + lane], qW3[kk * 32 + lane], s);
            #pragma unroll
            for (int o = 16; o > 0; o >>= 1) s += __shfl_xor_sync(0xffffffffu, s, o);
            if (lane == 0) out[b * Ag + a0 + a] = s + qb3[0];
        }
    }
}

// ---------------- launch ----------------
extern "C" void kernel_launch(void* const* d_in, const int* in_sizes, int n_in,
                              void* d_out, int out_size) {
    const float *x, *edge_attr, *action_tensor;
    const float *Wn, *bn, *gWl, *gbl, *gWr, *gbr, *gWe, *gatt, *gb;
    const float *aW1, *ab1, *aW2, *ab2, *qW1, *qb1, *qW2, *qb2, *qW3, *qb3;
    const int* edge_index;

    x             = (const float*)d_in[0];
    edge_attr     = (const float*)d_in[1];
    action_tensor = (const float*)d_in[2];

    if (in_sizes[3] > 100000) {
        edge_index = (const int*)d_in[3];
        Wn  = (const float*)d_in[6];  bn  = (const float*)d_in[7];
        gWl = (const float*)d_in[8];  gWr = (const float*)d_in[9];
        gWe = (const float*)d_in[10]; gatt= (const float*)d_in[11];
        gbl = (const float*)d_in[12]; gbr = (const float*)d_in[13];
        gb  = (const float*)d_in[14];
        aW1 = (const float*)d_in[15]; ab1 = (const float*)d_in[16];
        aW2 = (const float*)d_in[17]; ab2 = (const float*)d_in[18];
        qW1 = (const float*)d_in[19]; qb1 = (const float*)d_in[20];
        qW2 = (const float*)d_in[21]; qb2 = (const float*)d_in[22];
        qW3 = (const float*)d_in[23]; qb3 = (const float*)d_in[24];
    } else {
        Wn  = (const float*)d_in[3];  bn  = (const float*)d_in[4];
        gWl = (const float*)d_in[5];  gbl = (const float*)d_in[6];
        gWr = (const float*)d_in[7];  gbr = (const float*)d_in[8];
        gWe = (const float*)d_in[9];  gatt= (const float*)d_in[10];
        gb  = (const float*)d_in[11];
        aW1 = (const float*)d_in[12]; ab1 = (const float*)d_in[13];
        aW2 = (const float*)d_in[14]; ab2 = (const float*)d_in[15];
        qW1 = (const float*)d_in[16]; qb1 = (const float*)d_in[17];
        qW2 = (const float*)d_in[18]; qb2 = (const float*)d_in[19];
        qW3 = (const float*)d_in[20]; qb3 = (const float*)d_in[21];
        edge_index = (const int*)d_in[22];
    }

    const int SMEM_G = (128 * 132 + 128 * 256) * 4;                   // 198656
    const int SMEM_H = (16 * 516 + 2 * 16 * 128 + 3 * 128) * 4;       // 50944
    cudaFuncSetAttribute(k_gemm_dual, cudaFuncAttributeMaxDynamicSharedMemorySize, SMEM_G);
    cudaFuncSetAttribute(k_head,      cudaFuncAttributeMaxDynamicSharedMemorySize, SMEM_H);

    const int LOGIT_BLOCKS = (Eg + Nn) / 8;    // 1 warp/edge(+self), 8 warps/block

    k_zero<<<Nn / 256, 256>>>();                                   // 1
    k_inith<<<Nn * 32 / 256, 256>>>(x, Wn, bn);                    // 2
    k_hist<<<Eg / 256, 256>>>(edge_index, edge_attr);              // 3
    k_gemm_dual<<<Nn / 128, 512, SMEM_G>>>(gWl, gWr, gbl, gbr);    // 4  <- ncu capture target
    k_scan<<<1, 1024>>>();                                         // 5
    k_fill<<<Eg / 256, 256>>>(edge_index, edge_attr);              // 6
    k_logit<<<LOGIT_BLOCKS, 256>>>(gWe, gatt);                     // 7
    k_aggr<<<Nn / 8, 256>>>(gb);                                   // 8

    for (int l = 1; l < Lg; l++) {
        k_gemm_dual<<<Nn / 128, 512, SMEM_G>>>(gWl + l * HIDN * HIDN, gWr + l * HIDN * HIDN,
                                               gbl + l * HIDN, gbr + l * HIDN);
        k_logit<<<LOGIT_BLOCKS, 256>>>(gWe + l * HIDN, gatt + l * HIDN);
        k_aggr<<<Nn / 8, 256>>>(gb + l * HIDN);
    }

    k_pool<<<Bg * 8, 128>>>();
    k_head<<<Bg * 2, 256, SMEM_H>>>(action_tensor, aW1, ab1, aW2, ab2,
                                    qW1, qb1, qW2, qb2, qW3, qb3, (float*)d_out);
}

// round 5
// speedup vs baseline: 1.0803x; 1.0645x over previous
#include <cuda_runtime.h>
#include <math.h>
#include <stdint.h>

#define Nn   65536
#define Bg   64
#define NPG  1024
#define Ag   32
#define HIDN 128
#define Eg   262144
#define Lg   3
#define NEG  0.2f
#define NT   (Nn / 64)     // 1024 row tiles of 64
#define GPER 148           // persistent GEMM grid

// ---------------- scratch (device globals; no allocation allowed) ----------------
__device__ float g_h[Nn * HIDN];
__device__ float g_xl[Nn * HIDN];
__device__ float g_xr[Nn * HIDN];
__device__ int   g_indptr[Nn + 1];
__device__ int   g_cursor[Nn];
__device__ int   g_deg[Nn];
__device__ int   g_csr_src[Eg];
__device__ float g_csr_ea[Eg];
__device__ float g_partial[1024];
__device__ float g_ea_mean;
__device__ float g_pool_sum[Bg * HIDN];
__device__ float g_pool_max[Bg * HIDN];

// ---------------- packed f32x2 helpers (sm_103a FFMA2) ----------------
__device__ __forceinline__ unsigned long long pack2(float lo, float hi) {
    unsigned long long r;
    asm("mov.b64 %0, {%1, %2};" : "=l"(r) : "f"(lo), "f"(hi));
    return r;
}
__device__ __forceinline__ void ffma2(unsigned long long& d, unsigned long long a, unsigned long long b) {
    asm("fma.rn.f32x2 %0, %1, %2, %0;" : "+l"(d) : "l"(a), "l"(b));
}
__device__ __forceinline__ float2 unpack2(unsigned long long v) {
    float2 f;
    asm("mov.b64 {%0, %1}, %2;" : "=f"(f.x), "=f"(f.y) : "l"(v));
    return f;
}

// ---------------- launch 1: zero counters ----------------
__global__ void k_zero() {
    int i = blockIdx.x * blockDim.x + threadIdx.x;
    if (i < Nn) g_deg[i] = 0;
    if (i < Bg * HIDN) { g_pool_sum[i] = 0.f; g_pool_max[i] = 0.f; }
}

// ---------------- launch 2: h0 = relu(x @ Wn + bn), NF = 1 ----------------
__global__ void k_inith(const float* __restrict__ x, const float* __restrict__ Wn,
                        const float* __restrict__ bn) {
    int idx = blockIdx.x * blockDim.x + threadIdx.x;
    int node = idx >> 5;
    int c = (idx & 31) << 2;
    float xv = x[node];
    float4 w = *(const float4*)(Wn + c);
    float4 b = *(const float4*)(bn + c);
    float4 o;
    o.x = fmaxf(fmaf(xv, w.x, b.x), 0.f);
    o.y = fmaxf(fmaf(xv, w.y, b.y), 0.f);
    o.z = fmaxf(fmaf(xv, w.z, b.z), 0.f);
    o.w = fmaxf(fmaf(xv, w.w, b.w), 0.f);
    *(float4*)(g_h + node * HIDN + c) = o;
}

// ---------------- launch 3: degree histogram + edge_attr mean partials ----------------
__global__ void k_hist(const int* __restrict__ ei, const float* __restrict__ ea) {
    __shared__ float red[256];
    int e = blockIdx.x * 256 + threadIdx.x;
    atomicAdd(&g_deg[ei[Eg + e]], 1);
    red[threadIdx.x] = ea[e];
    __syncthreads();
    for (int st = 128; st > 0; st >>= 1) {
        if (threadIdx.x < st) red[threadIdx.x] += red[threadIdx.x + st];
        __syncthreads();
    }
    if (threadIdx.x == 0) g_partial[blockIdx.x] = red[0];
}

// ---------------- launch 4: persistent dual GEMM  xl = h@W1+b1, xr = h@W2+b2 ----------------
// grid = 148 persistent blocks; W resident in smem; A tiles (64 rows) double-buffered
__global__ __launch_bounds__(512) void k_gemm_dual(const float* __restrict__ W1,
                                                   const float* __restrict__ W2,
                                                   const float* __restrict__ b1,
                                                   const float* __restrict__ b2) {
    extern __shared__ float sm[];
    float* sW  = sm;                 // 128 x 256
    float* sA0 = sm + 128 * 256;     // 64 x 132
    float* sA1 = sA0 + 64 * 132;     // 64 x 132
    const int tid = threadIdx.x;

    // load W once (interleaved: cols 0..127 = W1, 128..255 = W2)
    for (int i = tid; i < 128 * 32; i += 512) {
        int k = i >> 5, c = (i & 31) << 2;
        *(float4*)(sW + k * 256 + c)       = *(const float4*)(W1 + k * HIDN + c);
        *(float4*)(sW + k * 256 + 128 + c) = *(const float4*)(W2 + k * HIDN + c);
    }

    // prologue: stage first A tile
    int t = blockIdx.x;
    float4 pre[4];
    {
        int row0 = t * 64;
        #pragma unroll
        for (int s = 0; s < 4; s++) {
            int idx = tid + s * 512;
            int r = idx >> 5, c = (idx & 31) << 2;
            pre[s] = *(const float4*)(g_h + (size_t)(row0 + r) * HIDN + c);
        }
        #pragma unroll
        for (int s = 0; s < 4; s++) {
            int idx = tid + s * 512;
            int r = idx >> 5, c = (idx & 31) << 2;
            *(float4*)(sA0 + r * 132 + c) = pre[s];
        }
    }
    __syncthreads();

    const int tx = tid & 15, ty = tid >> 4;      // ty 0..31 -> rows 2ty, 2ty+1
    const float* pW = sW + tx * 2;
    int buf = 0;

    for (; t < NT; t += GPER) {
        int tn = t + GPER;
        // prefetch next tile into regs (overlaps with compute)
        if (tn < NT) {
            int row0 = tn * 64;
            #pragma unroll
            for (int s = 0; s < 4; s++) {
                int idx = tid + s * 512;
                int r = idx >> 5, c = (idx & 31) << 2;
                pre[s] = *(const float4*)(g_h + (size_t)(row0 + r) * HIDN + c);
            }
        }

        const float* sA = buf ? sA1 : sA0;
        const float* pA = sA + ty * 2 * 132;

        unsigned long long acc[2][8];
        #pragma unroll
        for (int r = 0; r < 2; r++)
            #pragma unroll
            for (int p = 0; p < 8; p++) acc[r][p] = 0ull;

        #pragma unroll 2
        for (int k4 = 0; k4 < 128; k4 += 4) {
            float4 a4[2];
            a4[0] = *(const float4*)(pA + k4);
            a4[1] = *(const float4*)(pA + 132 + k4);
            #pragma unroll
            for (int kk = 0; kk < 4; kk++) {
                unsigned long long wv[8];
                #pragma unroll
                for (int p = 0; p < 8; p++)
                    wv[p] = *(const unsigned long long*)(pW + (size_t)(k4 + kk) * 256 + p * 32);
                #pragma unroll
                for (int r = 0; r < 2; r++) {
                    float a = (kk == 0) ? a4[r].x : (kk == 1) ? a4[r].y : (kk == 2) ? a4[r].z : a4[r].w;
                    unsigned long long av = pack2(a, a);
                    #pragma unroll
                    for (int p = 0; p < 8; p++) ffma2(acc[r][p], av, wv[p]);
                }
            }
        }

        // epilogue: bias + store
        int row0 = t * 64;
        #pragma unroll
        for (int p = 0; p < 8; p++) {
            int c = tx * 2 + p * 32;
            const float* bb = (c < 128) ? b1 : b2;
            float* outp     = (c < 128) ? g_xl : g_xr;
            int cc = c & 127;
            float2 bv = *(const float2*)(bb + cc);
            #pragma unroll
            for (int r = 0; r < 2; r++) {
                float2 v = unpack2(acc[r][p]);
                v.x += bv.x; v.y += bv.y;
                *(float2*)(outp + (size_t)(row0 + ty * 2 + r) * HIDN + cc) = v;
            }
        }

        // commit prefetched tile to the other buffer
        if (tn < NT) {
            float* sAn = buf ? sA0 : sA1;
            #pragma unroll
            for (int s = 0; s < 4; s++) {
                int idx = tid + s * 512;
                int r = idx >> 5, c = (idx & 31) << 2;
                *(float4*)(sAn + r * 132 + c) = pre[s];
            }
        }
        __syncthreads();
        buf ^= 1;
    }
}

// ---------------- launch 5: exclusive scan of degrees + finish edge_attr mean ----------------
__global__ __launch_bounds__(1024) void k_scan() {
    __shared__ int   ssum[1024];
    __shared__ float fred[1024];
    int t = threadIdx.x;

    fred[t] = g_partial[t];
    int base = t * 64;
    int s = 0;
    #pragma unroll 8
    for (int i = 0; i < 64; i++) s += g_deg[base + i];
    ssum[t] = s; __syncthreads();
    for (int off = 1; off < 1024; off <<= 1) {
        int v = (t >= off) ? ssum[t - off] : 0;
        __syncthreads();
        ssum[t] += v;
        __syncthreads();
    }
    int run = (t == 0) ? 0 : ssum[t - 1];
    for (int i = 0; i < 64; i++) {
        g_indptr[base + i] = run;
        g_cursor[base + i] = run;
        run += g_deg[base + i];
    }
    if (t == 1023) g_indptr[Nn] = run;

    for (int st = 512; st > 0; st >>= 1) {
        __syncthreads();
        if (t < st) fred[t] += fred[t + st];
    }
    __syncthreads();
    if (t == 0) g_ea_mean = fred[0] / (float)Eg;
}

// ---------------- launch 6: CSR fill ----------------
__global__ void k_fill(const int* __restrict__ ei, const float* __restrict__ ea) {
    int e = blockIdx.x * blockDim.x + threadIdx.x;
    if (e < Eg) {
        int d = ei[Eg + e];
        int pos = atomicAdd(&g_cursor[d], 1);
        g_csr_src[pos] = ei[e];
        g_csr_ea[pos]  = ea[e];
    }
}

// ---------------- edge aggregation: one warp/node; lane = (head, 4-channel chunk) ----------------
// head = lane>>3, channels = head*32 + (lane&7)*4 .. +3
// dot-reduce needs only 3 shuffle levels on ONE register; gathers are LDG.128
__global__ __launch_bounds__(256) void k_edge(const float* __restrict__ We,
                                              const float* __restrict__ att,
                                              const float* __restrict__ gb) {
    int node = (blockIdx.x * blockDim.x + threadIdx.x) >> 5;
    int lane = threadIdx.x & 31;
    if (node >= Nn) return;
    const int base = ((lane >> 3) << 5) + ((lane & 7) << 2);

    const float4 We4  = *(const float4*)(We + base);
    const float4 att4 = *(const float4*)(att + base);
    const float4 xr4  = *(const float4*)(g_xr + (size_t)node * HIDN + base);
    const float4 xl4  = *(const float4*)(g_xl + (size_t)node * HIDN + base);
    const float4 h4   = *(const float4*)(g_h  + (size_t)node * HIDN + base);
    const float  eam  = g_ea_mean;

    // self-loop logit
    float m;
    {
        float v0 = fmaf(eam, We4.x, xl4.x + xr4.x); v0 = v0 > 0.f ? v0 : NEG * v0;
        float v1 = fmaf(eam, We4.y, xl4.y + xr4.y); v1 = v1 > 0.f ? v1 : NEG * v1;
        float v2 = fmaf(eam, We4.z, xl4.z + xr4.z); v2 = v2 > 0.f ? v2 : NEG * v2;
        float v3 = fmaf(eam, We4.w, xl4.w + xr4.w); v3 = v3 > 0.f ? v3 : NEG * v3;
        float p = v0 * att4.x;
        p = fmaf(v1, att4.y, p);
        p = fmaf(v2, att4.z, p);
        p = fmaf(v3, att4.w, p);
        p += __shfl_xor_sync(0xffffffffu, p, 4);
        p += __shfl_xor_sync(0xffffffffu, p, 2);
        p += __shfl_xor_sync(0xffffffffu, p, 1);
        m = p;
    }
    float  s   = 1.f;
    float4 acc = xl4;

    const int e0 = g_indptr[node], e1 = g_indptr[node + 1];
    int e = e0;

    for (; e + 2 <= e1; e += 2) {
        int   s0 = g_csr_src[e],  s1 = g_csr_src[e + 1];
        float a0 = g_csr_ea[e],   a1 = g_csr_ea[e + 1];
        float4 x0 = __ldg((const float4*)(g_xl + (size_t)s0 * HIDN + base));
        float4 x1 = __ldg((const float4*)(g_xl + (size_t)s1 * HIDN + base));

        float v, q0, q1;
        v = fmaf(a0, We4.x, x0.x + xr4.x); v = v > 0.f ? v : NEG * v; q0 = v * att4.x;
        v = fmaf(a0, We4.y, x0.y + xr4.y); v = v > 0.f ? v : NEG * v; q0 = fmaf(v, att4.y, q0);
        v = fmaf(a0, We4.z, x0.z + xr4.z); v = v > 0.f ? v : NEG * v; q0 = fmaf(v, att4.z, q0);
        v = fmaf(a0, We4.w, x0.w + xr4.w); v = v > 0.f ? v : NEG * v; q0 = fmaf(v, att4.w, q0);
        v = fmaf(a1, We4.x, x1.x + xr4.x); v = v > 0.f ? v : NEG * v; q1 = v * att4.x;
        v = fmaf(a1, We4.y, x1.y + xr4.y); v = v > 0.f ? v : NEG * v; q1 = fmaf(v, att4.y, q1);
        v = fmaf(a1, We4.z, x1.z + xr4.z); v = v > 0.f ? v : NEG * v; q1 = fmaf(v, att4.z, q1);
        v = fmaf(a1, We4.w, x1.w + xr4.w); v = v > 0.f ? v : NEG * v; q1 = fmaf(v, att4.w, q1);

        q0 += __shfl_xor_sync(0xffffffffu, q0, 4);
        q1 += __shfl_xor_sync(0xffffffffu, q1, 4);
        q0 += __shfl_xor_sync(0xffffffffu, q0, 2);
        q1 += __shfl_xor_sync(0xffffffffu, q1, 2);
        q0 += __shfl_xor_sync(0xffffffffu, q0, 1);
        q1 += __shfl_xor_sync(0xffffffffu, q1, 1);

        float mn = fmaxf(m, fmaxf(q0, q1));
        float sc = __expf(m - mn);
        float p0 = __expf(q0 - mn);
        float p1 = __expf(q1 - mn);
        s = fmaf(s, sc, p0 + p1);
        acc.x = fmaf(acc.x, sc, fmaf(p0, x0.x, p1 * x1.x));
        acc.y = fmaf(acc.y, sc, fmaf(p0, x0.y, p1 * x1.y));
        acc.z = fmaf(acc.z, sc, fmaf(p0, x0.z, p1 * x1.z));
        acc.w = fmaf(acc.w, sc, fmaf(p0, x0.w, p1 * x1.w));
        m = mn;
    }
    if (e < e1) {
        int   s0 = g_csr_src[e];
        float a0 = g_csr_ea[e];
        float4 x0 = __ldg((const float4*)(g_xl + (size_t)s0 * HIDN + base));
        float v, q0;
        v = fmaf(a0, We4.x, x0.x + xr4.x); v = v > 0.f ? v : NEG * v; q0 = v * att4.x;
        v = fmaf(a0, We4.y, x0.y + xr4.y); v = v > 0.f ? v : NEG * v; q0 = fmaf(v, att4.y, q0);
        v = fmaf(a0, We4.z, x0.z + xr4.z); v = v > 0.f ? v : NEG * v; q0 = fmaf(v, att4.z, q0);
        v = fmaf(a0, We4.w, x0.w + xr4.w); v = v > 0.f ? v : NEG * v; q0 = fmaf(v, att4.w, q0);
        q0 += __shfl_xor_sync(0xffffffffu, q0, 4);
        q0 += __shfl_xor_sync(0xffffffffu, q0, 2);
        q0 += __shfl_xor_sync(0xffffffffu, q0, 1);
        float mn = fmaxf(m, q0);
        float sc = __expf(m - mn);
        float p0 = __expf(q0 - mn);
        s = fmaf(s, sc, p0);
        acc.x = fmaf(acc.x, sc, p0 * x0.x);
        acc.y = fmaf(acc.y, sc, p0 * x0.y);
        acc.z = fmaf(acc.z, sc, p0 * x0.z);
        acc.w = fmaf(acc.w, sc, p0 * x0.w);
        m = mn;
    }

    const float inv = 1.f / s;
    const float4 gb4 = *(const float4*)(gb + base);
    float4 o;
    o.x = fmaxf(fmaf(acc.x, inv, gb4.x), 0.f) + h4.x;
    o.y = fmaxf(fmaf(acc.y, inv, gb4.y), 0.f) + h4.y;
    o.z = fmaxf(fmaf(acc.z, inv, gb4.z), 0.f) + h4.z;
    o.w = fmaxf(fmaf(acc.w, inv, gb4.w), 0.f) + h4.w;
    *(float4*)(g_h + (size_t)node * HIDN + base) = o;
}

// ---------------- pooling (h >= 0, so int-bit atomicMax is valid) ----------------
__global__ void k_pool() {
    int b = blockIdx.x >> 3;
    int chunk = blockIdx.x & 7;
    int j = threadIdx.x;
    int node0 = b * NPG + chunk * 128;
    float s = 0.f, mx = 0.f;
    #pragma unroll 4
    for (int t = 0; t < 128; t++) {
        float v = g_h[(size_t)(node0 + t) * HIDN + j];
        s += v;
        mx = fmaxf(mx, v);
    }
    atomicAdd(&g_pool_sum[b * HIDN + j], s);
    atomicMax((int*)&g_pool_max[b * HIDN + j], __float_as_int(mx));
}

// ---------------- fused action encoder + Q head ----------------
__global__ __launch_bounds__(256) void k_head(const float* __restrict__ at,
        const float* __restrict__ aW1, const float* __restrict__ ab1,
        const float* __restrict__ aW2, const float* __restrict__ ab2,
        const float* __restrict__ qW1, const float* __restrict__ qb1,
        const float* __restrict__ qW2, const float* __restrict__ qb2,
        const float* __restrict__ qW3, const float* __restrict__ qb3,
        float* __restrict__ out) {
    extern __shared__ float sm[];
    float* IN   = sm;                 // 16 x 516
    float* S1   = IN + 16 * 516;      // 16 x 128
    float* S2   = S1 + 16 * 128;      // 16 x 128
    float* tcol = S2 + 16 * 128;      // 128
    float* ps   = tcol + 128;         // 128
    float* pm   = ps + 128;           // 128

    const int tid = threadIdx.x;
    const int b   = blockIdx.x >> 1;
    const int a0  = (blockIdx.x & 1) * 16;

    if (tid < 128) {
        ps[tid] = g_pool_sum[b * HIDN + tid];
        pm[tid] = g_pool_max[b * HIDN + tid];
    }
    __syncthreads();

    for (int idx = tid; idx < 16 * 512; idx += 256) {
        int a = idx >> 9, q = idx & 511;
        int slot = q >> 7, col = q & 127;
        int node = (int)at[(size_t)(b * Ag + a0 + a) * 7 + slot] + b * NPG;
        IN[a * 516 + q] = g_h[(size_t)node * HIDN + col];
    }
    for (int idx = tid; idx < 16 * 3; idx += 256) {
        int a = idx / 3, ms = idx % 3;
        IN[a * 516 + 512 + ms] = at[(size_t)(b * Ag + a0 + a) * 7 + 4 + ms];
    }
    if (tid < 128) {
        float acc = qb1[tid];
        for (int k = 0; k < 128; k++) {
            float sv = ps[k];
            acc = fmaf(sv, qW1[k * 128 + tid], acc);
            acc = fmaf(sv * (1.f / 1024.f), qW1[(128 + k) * 128 + tid], acc);
            acc = fmaf(pm[k], qW1[(256 + k) * 128 + tid], acc);
        }
        tcol[tid] = acc;
    }
    __syncthreads();

    const int col = tid & 127;
    const int ab  = (tid >> 7) * 8;

    {
        float acc[8]; float bias = ab1[col];
        #pragma unroll
        for (int a = 0; a < 8; a++) acc[a] = bias;
        for (int k = 0; k < 515; k++) {
            float w = aW1[k * 128 + col];
            #pragma unroll
            for (int a = 0; a < 8; a++) acc[a] = fmaf(IN[(ab + a) * 516 + k], w, acc[a]);
        }
        #pragma unroll
        for (int a = 0; a < 8; a++) S1[(ab + a) * 128 + col] = fmaxf(acc[a], 0.f);
    }
    __syncthreads();
    {
        float acc[8]; float bias = ab2[col];
        #pragma unroll
        for (int a = 0; a < 8; a++) acc[a] = bias;
        for (int k = 0; k < 128; k++) {
            float w = aW2[k * 128 + col];
            #pragma unroll
            for (int a = 0; a < 8; a++) acc[a] = fmaf(S1[(ab + a) * 128 + k], w, acc[a]);
        }
        #pragma unroll
        for (int a = 0; a < 8; a++) S2[(ab + a) * 128 + col] = fmaxf(acc[a], 0.f);
    }
    __syncthreads();
    {
        float acc[8]; float t = tcol[col];
        #pragma unroll
        for (int a = 0; a < 8; a++) acc[a] = t;
        for (int k = 0; k < 128; k++) {
            float w = qW1[(384 + k) * 128 + col];
            #pragma unroll
            for (int a = 0; a < 8; a++) acc[a] = fmaf(S2[(ab + a) * 128 + k], w, acc[a]);
        }
        #pragma unroll
        for (int a = 0; a < 8; a++) S1[(ab + a) * 128 + col] = fmaxf(acc[a], 0.f);
    }
    __syncthreads();
    {
        float acc[8]; float bias = qb2[col];
        #pragma unroll
        for (int a = 0; a < 8; a++) acc[a] = bias;
        for (int k = 0; k < 128; k++) {
            float w = qW2[k * 128 + col];
            #pragma unroll
            for (int a = 0; a < 8; a++) acc[a] = fmaf(S1[(ab + a) * 128 + k], w, acc[a]);
        }
        #pragma unroll
        for (int a = 0; a < 8; a++) S2[(ab + a) * 128 + col] = fmaxf(acc[a], 0.f);
    }
    __syncthreads();
    {
        int w_id = tid >> 5, lane = tid & 31;
        for (int a = w_id; a < 16; a += 8) {
            float s = 0.f;
            #pragma unroll
            for (int kk = 0; kk < 4; kk++)
                s = fmaf(S2[a * 128 + kk * 32 + lane], qW3[kk * 32 + lane], s);
            #pragma unroll
            for (int o = 16; o > 0; o >>= 1) s += __shfl_xor_sync(0xffffffffu, s, o);
            if (lane == 0) out[b * Ag + a0 + a] = s + qb3[0];
        }
    }
}

// ---------------- launch ----------------
extern "C" void kernel_launch(void* const* d_in, const int* in_sizes, int n_in,
                              void* d_out, int out_size) {
    const float *x, *edge_attr, *action_tensor;
    const float *Wn, *bn, *gWl, *gbl, *gWr, *gbr, *gWe, *gatt, *gb;
    const float *aW1, *ab1, *aW2, *ab2, *qW1, *qb1, *qW2, *qb2, *qW3, *qb3;
    const int* edge_index;

    x             = (const float*)d_in[0];
    edge_attr     = (const float*)d_in[1];
    action_tensor = (const float*)d_in[2];

    if (in_sizes[3] > 100000) {
        edge_index = (const int*)d_in[3];
        Wn  = (const float*)d_in[6];  bn  = (const float*)d_in[7];
        gWl = (const float*)d_in[8];  gWr = (const float*)d_in[9];
        gWe = (const float*)d_in[10]; gatt= (const float*)d_in[11];
        gbl = (const float*)d_in[12]; gbr = (const float*)d_in[13];
        gb  = (const float*)d_in[14];
        aW1 = (const float*)d_in[15]; ab1 = (const float*)d_in[16];
        aW2 = (const float*)d_in[17]; ab2 = (const float*)d_in[18];
        qW1 = (const float*)d_in[19]; qb1 = (const float*)d_in[20];
        qW2 = (const float*)d_in[21]; qb2 = (const float*)d_in[22];
        qW3 = (const float*)d_in[23]; qb3 = (const float*)d_in[24];
    } else {
        Wn  = (const float*)d_in[3];  bn  = (const float*)d_in[4];
        gWl = (const float*)d_in[5];  gbl = (const float*)d_in[6];
        gWr = (const float*)d_in[7];  gbr = (const float*)d_in[8];
        gWe = (const float*)d_in[9];  gatt= (const float*)d_in[10];
        gb  = (const float*)d_in[11];
        aW1 = (const float*)d_in[12]; ab1 = (const float*)d_in[13];
        aW2 = (const float*)d_in[14]; ab2 = (const float*)d_in[15];
        qW1 = (const float*)d_in[16]; qb1 = (const float*)d_in[17];
        qW2 = (const float*)d_in[18]; qb2 = (const float*)d_in[19];
        qW3 = (const float*)d_in[20]; qb3 = (const float*)d_in[21];
        edge_index = (const int*)d_in[22];
    }

    const int SMEM_G = (128 * 256 + 2 * 64 * 132) * 4;                // 198656
    const int SMEM_H = (16 * 516 + 2 * 16 * 128 + 3 * 128) * 4;       // 50944
    cudaFuncSetAttribute(k_gemm_dual, cudaFuncAttributeMaxDynamicSharedMemorySize, SMEM_G);
    cudaFuncSetAttribute(k_head,      cudaFuncAttributeMaxDynamicSharedMemorySize, SMEM_H);

    k_zero<<<Nn / 256, 256>>>();                                   // 1
    k_inith<<<Nn * 32 / 256, 256>>>(x, Wn, bn);                    // 2
    k_hist<<<Eg / 256, 256>>>(edge_index, edge_attr);              // 3
    k_gemm_dual<<<GPER, 512, SMEM_G>>>(gWl, gWr, gbl, gbr);        // 4  <- ncu capture target
    k_scan<<<1, 1024>>>();                                         // 5
    k_fill<<<Eg / 256, 256>>>(edge_index, edge_attr);              // 6
    k_edge<<<Nn / 8, 256>>>(gWe, gatt, gb);                        // 7

    for (int l = 1; l < Lg; l++) {
        k_gemm_dual<<<GPER, 512, SMEM_G>>>(gWl + l * HIDN * HIDN, gWr + l * HIDN * HIDN,
                                           gbl + l * HIDN, gbr + l * HIDN);
        k_edge<<<Nn / 8, 256>>>(gWe + l * HIDN, gatt + l * HIDN, gb + l * HIDN);
    }

    k_pool<<<Bg * 8, 128>>>();
    k_head<<<Bg * 2, 256, SMEM_H>>>(action_tensor, aW1, ab1, aW2, ab2,
                                    qW1, qb1, qW2, qb2, qW3, qb3, (float*)d_out);
}

// round 6
// speedup vs baseline: 1.2484x; 1.1556x over previous
#include <cuda_runtime.h>
#include <math.h>
#include <stdint.h>

#define Nn   65536
#define Bg   64
#define NPG  1024
#define Ag   32
#define HIDN 128
#define Eg   262144
#define Lg   3
#define NEG  0.2f

// ---------------- scratch (device globals; no allocation allowed) ----------------
__device__ float g_h[Nn * HIDN];
__device__ float g_xl[Nn * HIDN];
__device__ float g_xr[Nn * HIDN];
__device__ int   g_indptr[Nn + 1];
__device__ int   g_cursor[Nn];
__device__ int   g_deg[Nn];
__device__ int   g_csr_src[Eg];
__device__ float g_csr_ea[Eg];
__device__ float g_partial[1024];
__device__ float g_ea_mean;
__device__ float g_pool_sum[Bg * HIDN];
__device__ float g_pool_max[Bg * HIDN];

// ---------------- packed f32x2 helpers (sm_103a FFMA2) ----------------
__device__ __forceinline__ unsigned long long pack2(float lo, float hi) {
    unsigned long long r;
    asm("mov.b64 %0, {%1, %2};" : "=l"(r) : "f"(lo), "f"(hi));
    return r;
}
__device__ __forceinline__ void ffma2(unsigned long long& d, unsigned long long a, unsigned long long b) {
    asm("fma.rn.f32x2 %0, %1, %2, %0;" : "+l"(d) : "l"(a), "l"(b));
}
__device__ __forceinline__ float2 unpack2(unsigned long long v) {
    float2 f;
    asm("mov.b64 {%0, %1}, %2;" : "=f"(f.x), "=f"(f.y) : "l"(v));
    return f;
}

// ---------------- launch 1: zero counters ----------------
__global__ void k_zero() {
    int i = blockIdx.x * blockDim.x + threadIdx.x;
    if (i < Nn) g_deg[i] = 0;
    if (i < Bg * HIDN) { g_pool_sum[i] = 0.f; g_pool_max[i] = 0.f; }
}

// ---------------- launch 2: fused h0-init + degree histogram + edge_attr mean ----------------
// grid: Nn*32/256 = 8192 blocks. Blocks 0..1023 additionally process one edge per thread.
__global__ void k_prep(const float* __restrict__ x, const float* __restrict__ Wn,
                       const float* __restrict__ bn,
                       const int* __restrict__ ei, const float* __restrict__ ea) {
    int idx = blockIdx.x * 256 + threadIdx.x;
    // h0 = relu(x @ Wn + bn), NF = 1
    {
        int node = idx >> 5;
        int c = (idx & 31) << 2;
        float xv = x[node];
        float4 w = *(const float4*)(Wn + c);
        float4 b = *(const float4*)(bn + c);
        float4 o;
        o.x = fmaxf(fmaf(xv, w.x, b.x), 0.f);
        o.y = fmaxf(fmaf(xv, w.y, b.y), 0.f);
        o.z = fmaxf(fmaf(xv, w.z, b.z), 0.f);
        o.w = fmaxf(fmaf(xv, w.w, b.w), 0.f);
        *(float4*)(g_h + node * HIDN + c) = o;
    }
    // hist + mean partials on first Eg threads
    if (blockIdx.x < Eg / 256) {
        __shared__ float red[256];
        atomicAdd(&g_deg[ei[Eg + idx]], 1);
        red[threadIdx.x] = ea[idx];
        __syncthreads();
        for (int st = 128; st > 0; st >>= 1) {
            if (threadIdx.x < st) red[threadIdx.x] += red[threadIdx.x + st];
            __syncthreads();
        }
        if (threadIdx.x == 0) g_partial[blockIdx.x] = red[0];
    }
}

// ---------------- launch 3: exclusive scan of degrees + finish edge_attr mean ----------------
__global__ __launch_bounds__(1024) void k_scan() {
    __shared__ int   ssum[1024];
    __shared__ float fred[1024];
    int t = threadIdx.x;

    fred[t] = g_partial[t];
    int base = t * 64;
    int s = 0;
    #pragma unroll 8
    for (int i = 0; i < 64; i++) s += g_deg[base + i];
    ssum[t] = s; __syncthreads();
    for (int off = 1; off < 1024; off <<= 1) {
        int v = (t >= off) ? ssum[t - off] : 0;
        __syncthreads();
        ssum[t] += v;
        __syncthreads();
    }
    int run = (t == 0) ? 0 : ssum[t - 1];
    for (int i = 0; i < 64; i++) {
        g_indptr[base + i] = run;
        g_cursor[base + i] = run;
        run += g_deg[base + i];
    }
    if (t == 1023) g_indptr[Nn] = run;

    for (int st = 512; st > 0; st >>= 1) {
        __syncthreads();
        if (t < st) fred[t] += fred[t + st];
    }
    __syncthreads();
    if (t == 0) g_ea_mean = fred[0] / (float)Eg;
}

// ---------------- launch 4: dual GEMM  xl = h@W1+b1, xr = h@W2+b2 (round-4 best shape) ----------------
__global__ __launch_bounds__(512) void k_gemm_dual(const float* __restrict__ W1,
                                                   const float* __restrict__ W2,
                                                   const float* __restrict__ b1,
                                                   const float* __restrict__ b2) {
    extern __shared__ float sm[];
    float* sA = sm;               // 128 x 132
    float* sW = sm + 128 * 132;   // 128 x 256
    const int tid  = threadIdx.x;
    const int row0 = blockIdx.x * 128;

    for (int i = tid; i < 128 * 32; i += 512) {
        int r = i >> 5, c = (i & 31) << 2;
        *(float4*)(sA + r * 132 + c) = *(const float4*)(g_h + (size_t)(row0 + r) * HIDN + c);
        *(float4*)(sW + r * 256 + c)       = *(const float4*)(W1 + r * HIDN + c);
        *(float4*)(sW + r * 256 + 128 + c) = *(const float4*)(W2 + r * HIDN + c);
    }
    __syncthreads();

    const int tx = tid & 15, ty = tid >> 4;
    unsigned long long acc[4][8];
    #pragma unroll
    for (int r = 0; r < 4; r++)
        #pragma unroll
        for (int p = 0; p < 8; p++) acc[r][p] = 0ull;

    const float* pA = sA + ty * 4 * 132;
    const float* pW = sW + tx * 2;

    #pragma unroll 2
    for (int k4 = 0; k4 < 128; k4 += 4) {
        float4 a4[4];
        #pragma unroll
        for (int r = 0; r < 4; r++) a4[r] = *(const float4*)(pA + r * 132 + k4);

        #pragma unroll
        for (int kk = 0; kk < 4; kk++) {
            unsigned long long wv[8];
            #pragma unroll
            for (int p = 0; p < 8; p++)
                wv[p] = *(const unsigned long long*)(pW + (size_t)(k4 + kk) * 256 + p * 32);
            #pragma unroll
            for (int r = 0; r < 4; r++) {
                float a = (kk == 0) ? a4[r].x : (kk == 1) ? a4[r].y : (kk == 2) ? a4[r].z : a4[r].w;
                unsigned long long av = pack2(a, a);
                #pragma unroll
                for (int p = 0; p < 8; p++) ffma2(acc[r][p], av, wv[p]);
            }
        }
    }

    #pragma unroll
    for (int p = 0; p < 8; p++) {
        int c = tx * 2 + p * 32;
        const float* bb = (c < 128) ? b1 : b2;
        float* outp     = (c < 128) ? g_xl : g_xr;
        int cc = c & 127;
        float2 bv = *(const float2*)(bb + cc);
        #pragma unroll
        for (int r = 0; r < 4; r++) {
            float2 v = unpack2(acc[r][p]);
            v.x += bv.x; v.y += bv.y;
            *(float2*)(outp + (size_t)(row0 + ty * 4 + r) * HIDN + cc) = v;
        }
    }
}

// ---------------- launch 5: CSR fill ----------------
__global__ void k_fill(const int* __restrict__ ei, const float* __restrict__ ea) {
    int e = blockIdx.x * blockDim.x + threadIdx.x;
    if (e < Eg) {
        int d = ei[Eg + e];
        int pos = atomicAdd(&g_cursor[d], 1);
        g_csr_src[pos] = ei[e];
        g_csr_ea[pos]  = ea[e];
    }
}

// ---------------- edge aggregation: warp/node; lane=(head, 4-chan); fixed-offset softmax ----------------
// Softmax is shift-invariant: use the self-loop logit as a FIXED offset, eliminating the
// loop-carried max/rescale chain. Per-edge update = exp + 5 independent FMAs.
__global__ __launch_bounds__(256) void k_edge(const float* __restrict__ We,
                                              const float* __restrict__ att,
                                              const float* __restrict__ gb) {
    int node = (blockIdx.x * blockDim.x + threadIdx.x) >> 5;
    int lane = threadIdx.x & 31;
    if (node >= Nn) return;
    const int base = ((lane >> 3) << 5) + ((lane & 7) << 2);

    const float4 We4  = *(const float4*)(We + base);
    const float4 att4 = *(const float4*)(att + base);
    const float4 xr4  = *(const float4*)(g_xr + (size_t)node * HIDN + base);
    const float4 xl4  = *(const float4*)(g_xl + (size_t)node * HIDN + base);
    const float4 h4   = *(const float4*)(g_h  + (size_t)node * HIDN + base);
    const float  eam  = g_ea_mean;

    // self-loop logit -> fixed offset m
    float m;
    {
        float v0 = fmaf(eam, We4.x, xl4.x + xr4.x); v0 = v0 > 0.f ? v0 : NEG * v0;
        float v1 = fmaf(eam, We4.y, xl4.y + xr4.y); v1 = v1 > 0.f ? v1 : NEG * v1;
        float v2 = fmaf(eam, We4.z, xl4.z + xr4.z); v2 = v2 > 0.f ? v2 : NEG * v2;
        float v3 = fmaf(eam, We4.w, xl4.w + xr4.w); v3 = v3 > 0.f ? v3 : NEG * v3;
        float p = v0 * att4.x;
        p = fmaf(v1, att4.y, p);
        p = fmaf(v2, att4.z, p);
        p = fmaf(v3, att4.w, p);
        p += __shfl_xor_sync(0xffffffffu, p, 4);
        p += __shfl_xor_sync(0xffffffffu, p, 2);
        p += __shfl_xor_sync(0xffffffffu, p, 1);
        m = p;
    }
    float  s   = 1.f;                       // exp(m - m)
    float4 acc = xl4;

    const int e0 = g_indptr[node], e1 = g_indptr[node + 1];
    int e = e0;

    for (; e + 2 <= e1; e += 2) {
        int   s0 = g_csr_src[e],  s1 = g_csr_src[e + 1];
        float a0 = g_csr_ea[e],   a1 = g_csr_ea[e + 1];
        float4 x0 = __ldg((const float4*)(g_xl + (size_t)s0 * HIDN + base));
        float4 x1 = __ldg((const float4*)(g_xl + (size_t)s1 * HIDN + base));

        float v, q0, q1;
        v = fmaf(a0, We4.x, x0.x + xr4.x); v = v > 0.f ? v : NEG * v; q0 = v * att4.x;
        v = fmaf(a0, We4.y, x0.y + xr4.y); v = v > 0.f ? v : NEG * v; q0 = fmaf(v, att4.y, q0);
        v = fmaf(a0, We4.z, x0.z + xr4.z); v = v > 0.f ? v : NEG * v; q0 = fmaf(v, att4.z, q0);
        v = fmaf(a0, We4.w, x0.w + xr4.w); v = v > 0.f ? v : NEG * v; q0 = fmaf(v, att4.w, q0);
        v = fmaf(a1, We4.x, x1.x + xr4.x); v = v > 0.f ? v : NEG * v; q1 = v * att4.x;
        v = fmaf(a1, We4.y, x1.y + xr4.y); v = v > 0.f ? v : NEG * v; q1 = fmaf(v, att4.y, q1);
        v = fmaf(a1, We4.z, x1.z + xr4.z); v = v > 0.f ? v : NEG * v; q1 = fmaf(v, att4.z, q1);
        v = fmaf(a1, We4.w, x1.w + xr4.w); v = v > 0.f ? v : NEG * v; q1 = fmaf(v, att4.w, q1);

        q0 += __shfl_xor_sync(0xffffffffu, q0, 4);
        q1 += __shfl_xor_sync(0xffffffffu, q1, 4);
        q0 += __shfl_xor_sync(0xffffffffu, q0, 2);
        q1 += __shfl_xor_sync(0xffffffffu, q1, 2);
        q0 += __shfl_xor_sync(0xffffffffu, q0, 1);
        q1 += __shfl_xor_sync(0xffffffffu, q1, 1);

        float p0 = __expf(q0 - m);
        float p1 = __expf(q1 - m);
        s += p0 + p1;
        acc.x = fmaf(p0, x0.x, fmaf(p1, x1.x, acc.x));
        acc.y = fmaf(p0, x0.y, fmaf(p1, x1.y, acc.y));
        acc.z = fmaf(p0, x0.z, fmaf(p1, x1.z, acc.z));
        acc.w = fmaf(p0, x0.w, fmaf(p1, x1.w, acc.w));
    }
    if (e < e1) {
        int   s0 = g_csr_src[e];
        float a0 = g_csr_ea[e];
        float4 x0 = __ldg((const float4*)(g_xl + (size_t)s0 * HIDN + base));
        float v, q0;
        v = fmaf(a0, We4.x, x0.x + xr4.x); v = v > 0.f ? v : NEG * v; q0 = v * att4.x;
        v = fmaf(a0, We4.y, x0.y + xr4.y); v = v > 0.f ? v : NEG * v; q0 = fmaf(v, att4.y, q0);
        v = fmaf(a0, We4.z, x0.z + xr4.z); v = v > 0.f ? v : NEG * v; q0 = fmaf(v, att4.z, q0);
        v = fmaf(a0, We4.w, x0.w + xr4.w); v = v > 0.f ? v : NEG * v; q0 = fmaf(v, att4.w, q0);
        q0 += __shfl_xor_sync(0xffffffffu, q0, 4);
        q0 += __shfl_xor_sync(0xffffffffu, q0, 2);
        q0 += __shfl_xor_sync(0xffffffffu, q0, 1);
        float p0 = __expf(q0 - m);
        s += p0;
        acc.x = fmaf(p0, x0.x, acc.x);
        acc.y = fmaf(p0, x0.y, acc.y);
        acc.z = fmaf(p0, x0.z, acc.z);
        acc.w = fmaf(p0, x0.w, acc.w);
    }

    const float inv = 1.f / s;
    const float4 gb4 = *(const float4*)(gb + base);
    float4 o;
    o.x = fmaxf(fmaf(acc.x, inv, gb4.x), 0.f) + h4.x;
    o.y = fmaxf(fmaf(acc.y, inv, gb4.y), 0.f) + h4.y;
    o.z = fmaxf(fmaf(acc.z, inv, gb4.z), 0.f) + h4.z;
    o.w = fmaxf(fmaf(acc.w, inv, gb4.w), 0.f) + h4.w;
    *(float4*)(g_h + (size_t)node * HIDN + base) = o;
}

// ---------------- pooling (h >= 0, so int-bit atomicMax is valid) ----------------
__global__ void k_pool() {
    int b = blockIdx.x >> 3;
    int chunk = blockIdx.x & 7;
    int j = threadIdx.x;
    int node0 = b * NPG + chunk * 128;
    float s = 0.f, mx = 0.f;
    #pragma unroll 4
    for (int t = 0; t < 128; t++) {
        float v = g_h[(size_t)(node0 + t) * HIDN + j];
        s += v;
        mx = fmaxf(mx, v);
    }
    atomicAdd(&g_pool_sum[b * HIDN + j], s);
    atomicMax((int*)&g_pool_max[b * HIDN + j], __float_as_int(mx));
}

// ---------------- fused action encoder + Q head ----------------
__global__ __launch_bounds__(256) void k_head(const float* __restrict__ at,
        const float* __restrict__ aW1, const float* __restrict__ ab1,
        const float* __restrict__ aW2, const float* __restrict__ ab2,
        const float* __restrict__ qW1, const float* __restrict__ qb1,
        const float* __restrict__ qW2, const float* __restrict__ qb2,
        const float* __restrict__ qW3, const float* __restrict__ qb3,
        float* __restrict__ out) {
    extern __shared__ float sm[];
    float* IN   = sm;                 // 16 x 516
    float* S1   = IN + 16 * 516;      // 16 x 128
    float* S2   = S1 + 16 * 128;      // 16 x 128
    float* tcol = S2 + 16 * 128;      // 128
    float* ps   = tcol + 128;         // 128
    float* pm   = ps + 128;           // 128

    const int tid = threadIdx.x;
    const int b   = blockIdx.x >> 1;
    const int a0  = (blockIdx.x & 1) * 16;

    if (tid < 128) {
        ps[tid] = g_pool_sum[b * HIDN + tid];
        pm[tid] = g_pool_max[b * HIDN + tid];
    }
    __syncthreads();

    for (int idx = tid; idx < 16 * 512; idx += 256) {
        int a = idx >> 9, q = idx & 511;
        int slot = q >> 7, col = q & 127;
        int node = (int)at[(size_t)(b * Ag + a0 + a) * 7 + slot] + b * NPG;
        IN[a * 516 + q] = g_h[(size_t)node * HIDN + col];
    }
    for (int idx = tid; idx < 16 * 3; idx += 256) {
        int a = idx / 3, ms = idx % 3;
        IN[a * 516 + 512 + ms] = at[(size_t)(b * Ag + a0 + a) * 7 + 4 + ms];
    }
    if (tid < 128) {
        float acc = qb1[tid];
        for (int k = 0; k < 128; k++) {
            float sv = ps[k];
            acc = fmaf(sv, qW1[k * 128 + tid], acc);
            acc = fmaf(sv * (1.f / 1024.f), qW1[(128 + k) * 128 + tid], acc);
            acc = fmaf(pm[k], qW1[(256 + k) * 128 + tid], acc);
        }
        tcol[tid] = acc;
    }
    __syncthreads();

    const int col = tid & 127;
    const int ab  = (tid >> 7) * 8;

    {
        float acc[8]; float bias = ab1[col];
        #pragma unroll
        for (int a = 0; a < 8; a++) acc[a] = bias;
        for (int k = 0; k < 515; k++) {
            float w = aW1[k * 128 + col];
            #pragma unroll
            for (int a = 0; a < 8; a++) acc[a] = fmaf(IN[(ab + a) * 516 + k], w, acc[a]);
        }
        #pragma unroll
        for (int a = 0; a < 8; a++) S1[(ab + a) * 128 + col] = fmaxf(acc[a], 0.f);
    }
    __syncthreads();
    {
        float acc[8]; float bias = ab2[col];
        #pragma unroll
        for (int a = 0; a < 8; a++) acc[a] = bias;
        for (int k = 0; k < 128; k++) {
            float w = aW2[k * 128 + col];
            #pragma unroll
            for (int a = 0; a < 8; a++) acc[a] = fmaf(S1[(ab + a) * 128 + k], w, acc[a]);
        }
        #pragma unroll
        for (int a = 0; a < 8; a++) S2[(ab + a) * 128 + col] = fmaxf(acc[a], 0.f);
    }
    __syncthreads();
    {
        float acc[8]; float t = tcol[col];
        #pragma unroll
        for (int a = 0; a < 8; a++) acc[a] = t;
        for (int k = 0; k < 128; k++) {
            float w = qW1[(384 + k) * 128 + col];
            #pragma unroll
            for (int a = 0; a < 8; a++) acc[a] = fmaf(S2[(ab + a) * 128 + k], w, acc[a]);
        }
        #pragma unroll
        for (int a = 0; a < 8; a++) S1[(ab + a) * 128 + col] = fmaxf(acc[a], 0.f);
    }
    __syncthreads();
    {
        float acc[8]; float bias = qb2[col];
        #pragma unroll
        for (int a = 0; a < 8; a++) acc[a] = bias;
        for (int k = 0; k < 128; k++) {
            float w = qW2[k * 128 + col];
            #pragma unroll
            for (int a = 0; a < 8; a++) acc[a] = fmaf(S1[(ab + a) * 128 + k], w, acc[a]);
        }
        #pragma unroll
        for (int a = 0; a < 8; a++) S2[(ab + a) * 128 + col] = fmaxf(acc[a], 0.f);
    }
    __syncthreads();
    {
        int w_id = tid >> 5, lane = tid & 31;
        for (int a = w_id; a < 16; a += 8) {
            float s = 0.f;
            #pragma unroll
            for (int kk = 0; kk < 4; kk++)
                s = fmaf(S2[a * 128 + kk * 32 + lane], qW3[kk * 32 + lane], s);
            #pragma unroll
            for (int o = 16; o > 0; o >>= 1) s += __shfl_xor_sync(0xffffffffu, s, o);
            if (lane == 0) out[b * Ag + a0 + a] = s + qb3[0];
        }
    }
}

// ---------------- launch ----------------
extern "C" void kernel_launch(void* const* d_in, const int* in_sizes, int n_in,
                              void* d_out, int out_size) {
    const float *x, *edge_attr, *action_tensor;
    const float *Wn, *bn, *gWl, *gbl, *gWr, *gbr, *gWe, *gatt, *gb;
    const float *aW1, *ab1, *aW2, *ab2, *qW1, *qb1, *qW2, *qb2, *qW3, *qb3;
    const int* edge_index;

    x             = (const float*)d_in[0];
    edge_attr     = (const float*)d_in[1];
    action_tensor = (const float*)d_in[2];

    if (in_sizes[3] > 100000) {
        edge_index = (const int*)d_in[3];
        Wn  = (const float*)d_in[6];  bn  = (const float*)d_in[7];
        gWl = (const float*)d_in[8];  gWr = (const float*)d_in[9];
        gWe = (const float*)d_in[10]; gatt= (const float*)d_in[11];
        gbl = (const float*)d_in[12]; gbr = (const float*)d_in[13];
        gb  = (const float*)d_in[14];
        aW1 = (const float*)d_in[15]; ab1 = (const float*)d_in[16];
        aW2 = (const float*)d_in[17]; ab2 = (const float*)d_in[18];
        qW1 = (const float*)d_in[19]; qb1 = (const float*)d_in[20];
        qW2 = (const float*)d_in[21]; qb2 = (const float*)d_in[22];
        qW3 = (const float*)d_in[23]; qb3 = (const float*)d_in[24];
    } else {
        Wn  = (const float*)d_in[3];  bn  = (const float*)d_in[4];
        gWl = (const float*)d_in[5];  gbl = (const float*)d_in[6];
        gWr = (const float*)d_in[7];  gbr = (const float*)d_in[8];
        gWe = (const float*)d_in[9];  gatt= (const float*)d_in[10];
        gb  = (const float*)d_in[11];
        aW1 = (const float*)d_in[12]; ab1 = (const float*)d_in[13];
        aW2 = (const float*)d_in[14]; ab2 = (const float*)d_in[15];
        qW1 = (const float*)d_in[16]; qb1 = (const float*)d_in[17];
        qW2 = (const float*)d_in[18]; qb2 = (const float*)d_in[19];
        qW3 = (const float*)d_in[20]; qb3 = (const float*)d_in[21];
        edge_index = (const int*)d_in[22];
    }

    const int SMEM_G = (128 * 132 + 128 * 256) * 4;                   // 198656
    const int SMEM_H = (16 * 516 + 2 * 16 * 128 + 3 * 128) * 4;       // 50944
    cudaFuncSetAttribute(k_gemm_dual, cudaFuncAttributeMaxDynamicSharedMemorySize, SMEM_G);
    cudaFuncSetAttribute(k_head,      cudaFuncAttributeMaxDynamicSharedMemorySize, SMEM_H);

    k_zero<<<Nn / 256, 256>>>();                                       // 1
    k_prep<<<Nn * 32 / 256, 256>>>(x, Wn, bn, edge_index, edge_attr);  // 2
    k_scan<<<1, 1024>>>();                                             // 3
    k_gemm_dual<<<Nn / 128, 512, SMEM_G>>>(gWl, gWr, gbl, gbr);        // 4 <- ncu capture target
    k_fill<<<Eg / 256, 256>>>(edge_index, edge_attr);                  // 5
    k_edge<<<Nn / 8, 256>>>(gWe, gatt, gb);                            // 6

    for (int l = 1; l < Lg; l++) {
        k_gemm_dual<<<Nn / 128, 512, SMEM_G>>>(gWl + l * HIDN * HIDN, gWr + l * HIDN * HIDN,
                                               gbl + l * HIDN, gbr + l * HIDN);
        k_edge<<<Nn / 8, 256>>>(gWe + l * HIDN, gatt + l * HIDN, gb + l * HIDN);
    }

    k_pool<<<Bg * 8, 128>>>();
    k_head<<<Bg * 2, 256, SMEM_H>>>(action_tensor, aW1, ab1, aW2, ab2,
                                    qW1, qb1, qW2, qb2, qW3, qb3, (float*)d_out);
}

// round 7
// speedup vs baseline: 1.3389x; 1.0726x over previous
#include <cuda_runtime.h>
#include <cuda_fp16.h>
#include <math.h>
#include <stdint.h>

#define Nn   65536
#define Bg   64
#define NPG  1024
#define Ag   32
#define HIDN 128
#define Eg   262144
#define Lg   3
#define NEG  0.2f

// ---------------- scratch (device globals; no allocation allowed) ----------------
__device__ float  g_h[Nn * HIDN];
__device__ __half g_xlh[Nn * HIDN];     // fp16 xl (gathered per edge)
__device__ __half g_xrh[Nn * HIDN];     // fp16 xr (read per node)
__device__ int    g_indptr[Nn + 1];
__device__ int    g_cursor[Nn];
__device__ int    g_deg[Nn];
__device__ int    g_csr_src[Eg];
__device__ float  g_csr_ea[Eg];
__device__ float  g_partial[1024];
__device__ float  g_ea_mean;
__device__ float  g_pool_sum[Bg * HIDN];
__device__ float  g_pool_max[Bg * HIDN];

// ---------------- packed f32x2 helpers (sm_103a FFMA2) ----------------
__device__ __forceinline__ unsigned long long pack2(float lo, float hi) {
    unsigned long long r;
    asm("mov.b64 %0, {%1, %2};" : "=l"(r) : "f"(lo), "f"(hi));
    return r;
}
__device__ __forceinline__ void ffma2(unsigned long long& d, unsigned long long a, unsigned long long b) {
    asm("fma.rn.f32x2 %0, %1, %2, %0;" : "+l"(d) : "l"(a), "l"(b));
}
__device__ __forceinline__ float2 unpack2(unsigned long long v) {
    float2 f;
    asm("mov.b64 {%0, %1}, %2;" : "=f"(f.x), "=f"(f.y) : "l"(v));
    return f;
}
__device__ __forceinline__ float4 h4_to_f4(uint2 u) {
    __half2 a = *(__half2*)&u.x;
    __half2 b = *(__half2*)&u.y;
    float2 fa = __half22float2(a);
    float2 fb = __half22float2(b);
    return make_float4(fa.x, fa.y, fb.x, fb.y);
}

// ---------------- launch 1: zero counters ----------------
__global__ void k_zero() {
    int i = blockIdx.x * blockDim.x + threadIdx.x;
    if (i < Nn) g_deg[i] = 0;
    if (i < Bg * HIDN) { g_pool_sum[i] = 0.f; g_pool_max[i] = 0.f; }
}

// ---------------- launch 2: fused h0-init + degree histogram + edge_attr mean ----------------
__global__ void k_prep(const float* __restrict__ x, const float* __restrict__ Wn,
                       const float* __restrict__ bn,
                       const int* __restrict__ ei, const float* __restrict__ ea) {
    int idx = blockIdx.x * 256 + threadIdx.x;
    {
        int node = idx >> 5;
        int c = (idx & 31) << 2;
        float xv = x[node];
        float4 w = *(const float4*)(Wn + c);
        float4 b = *(const float4*)(bn + c);
        float4 o;
        o.x = fmaxf(fmaf(xv, w.x, b.x), 0.f);
        o.y = fmaxf(fmaf(xv, w.y, b.y), 0.f);
        o.z = fmaxf(fmaf(xv, w.z, b.z), 0.f);
        o.w = fmaxf(fmaf(xv, w.w, b.w), 0.f);
        *(float4*)(g_h + node * HIDN + c) = o;
    }
    if (blockIdx.x < Eg / 256) {
        __shared__ float red[256];
        atomicAdd(&g_deg[ei[Eg + idx]], 1);
        red[threadIdx.x] = ea[idx];
        __syncthreads();
        for (int st = 128; st > 0; st >>= 1) {
            if (threadIdx.x < st) red[threadIdx.x] += red[threadIdx.x + st];
            __syncthreads();
        }
        if (threadIdx.x == 0) g_partial[blockIdx.x] = red[0];
    }
}

// ---------------- launch 3: exclusive scan of degrees + finish edge_attr mean ----------------
__global__ __launch_bounds__(1024) void k_scan() {
    __shared__ int   ssum[1024];
    __shared__ float fred[1024];
    int t = threadIdx.x;

    fred[t] = g_partial[t];
    int base = t * 64;
    int s = 0;
    #pragma unroll 8
    for (int i = 0; i < 64; i++) s += g_deg[base + i];
    ssum[t] = s; __syncthreads();
    for (int off = 1; off < 1024; off <<= 1) {
        int v = (t >= off) ? ssum[t - off] : 0;
        __syncthreads();
        ssum[t] += v;
        __syncthreads();
    }
    int run = (t == 0) ? 0 : ssum[t - 1];
    for (int i = 0; i < 64; i++) {
        g_indptr[base + i] = run;
        g_cursor[base + i] = run;
        run += g_deg[base + i];
    }
    if (t == 1023) g_indptr[Nn] = run;

    for (int st = 512; st > 0; st >>= 1) {
        __syncthreads();
        if (t < st) fred[t] += fred[t + st];
    }
    __syncthreads();
    if (t == 0) g_ea_mean = fred[0] / (float)Eg;
}

// ---------------- launch 4: dual GEMM -> fp16 outputs  xl = h@W1+b1, xr = h@W2+b2 ----------------
__global__ __launch_bounds__(512) void k_gemm_dual(const float* __restrict__ W1,
                                                   const float* __restrict__ W2,
                                                   const float* __restrict__ b1,
                                                   const float* __restrict__ b2) {
    extern __shared__ float sm[];
    float* sA = sm;               // 128 x 132
    float* sW = sm + 128 * 132;   // 128 x 256
    const int tid  = threadIdx.x;
    const int row0 = blockIdx.x * 128;

    for (int i = tid; i < 128 * 32; i += 512) {
        int r = i >> 5, c = (i & 31) << 2;
        *(float4*)(sA + r * 132 + c) = *(const float4*)(g_h + (size_t)(row0 + r) * HIDN + c);
        *(float4*)(sW + r * 256 + c)       = *(const float4*)(W1 + r * HIDN + c);
        *(float4*)(sW + r * 256 + 128 + c) = *(const float4*)(W2 + r * HIDN + c);
    }
    __syncthreads();

    const int tx = tid & 15, ty = tid >> 4;
    unsigned long long acc[4][8];
    #pragma unroll
    for (int r = 0; r < 4; r++)
        #pragma unroll
        for (int p = 0; p < 8; p++) acc[r][p] = 0ull;

    const float* pA = sA + ty * 4 * 132;
    const float* pW = sW + tx * 2;

    #pragma unroll 2
    for (int k4 = 0; k4 < 128; k4 += 4) {
        float4 a4[4];
        #pragma unroll
        for (int r = 0; r < 4; r++) a4[r] = *(const float4*)(pA + r * 132 + k4);

        #pragma unroll
        for (int kk = 0; kk < 4; kk++) {
            unsigned long long wv[8];
            #pragma unroll
            for (int p = 0; p < 8; p++)
                wv[p] = *(const unsigned long long*)(pW + (size_t)(k4 + kk) * 256 + p * 32);
            #pragma unroll
            for (int r = 0; r < 4; r++) {
                float a = (kk == 0) ? a4[r].x : (kk == 1) ? a4[r].y : (kk == 2) ? a4[r].z : a4[r].w;
                unsigned long long av = pack2(a, a);
                #pragma unroll
                for (int p = 0; p < 8; p++) ffma2(acc[r][p], av, wv[p]);
            }
        }
    }

    #pragma unroll
    for (int p = 0; p < 8; p++) {
        int c = tx * 2 + p * 32;
        const float* bb  = (c < 128) ? b1 : b2;
        __half* outp     = (c < 128) ? g_xlh : g_xrh;
        int cc = c & 127;
        float2 bv = *(const float2*)(bb + cc);
        #pragma unroll
        for (int r = 0; r < 4; r++) {
            float2 v = unpack2(acc[r][p]);
            v.x += bv.x; v.y += bv.y;
            *(__half2*)(outp + (size_t)(row0 + ty * 4 + r) * HIDN + cc) = __floats2half2_rn(v.x, v.y);
        }
    }
}

// ---------------- launch 5: CSR fill ----------------
__global__ void k_fill(const int* __restrict__ ei, const float* __restrict__ ea) {
    int e = blockIdx.x * blockDim.x + threadIdx.x;
    if (e < Eg) {
        int d = ei[Eg + e];
        int pos = atomicAdd(&g_cursor[d], 1);
        g_csr_src[pos] = ei[e];
        g_csr_ea[pos]  = ea[e];
    }
}

// ---------------- edge aggregation: warp/node; lane=(head,4-chan); fp16 gathers; fixed-offset softmax ----------------
__global__ __launch_bounds__(256) void k_edge(const float* __restrict__ We,
                                              const float* __restrict__ att,
                                              const float* __restrict__ gb) {
    int node = (blockIdx.x * blockDim.x + threadIdx.x) >> 5;
    int lane = threadIdx.x & 31;
    if (node >= Nn) return;
    const int base = ((lane >> 3) << 5) + ((lane & 7) << 2);

    const float4 We4  = *(const float4*)(We + base);
    const float4 att4 = *(const float4*)(att + base);
    const float4 xr4  = h4_to_f4(*(const uint2*)(g_xrh + (size_t)node * HIDN + base));
    const float4 xl4  = h4_to_f4(*(const uint2*)(g_xlh + (size_t)node * HIDN + base));
    const float4 h4   = *(const float4*)(g_h + (size_t)node * HIDN + base);
    const float  eam  = g_ea_mean;

    // self-loop logit -> fixed offset m (softmax shift-invariant)
    float m;
    {
        float v0 = fmaf(eam, We4.x, xl4.x + xr4.x); v0 = v0 > 0.f ? v0 : NEG * v0;
        float v1 = fmaf(eam, We4.y, xl4.y + xr4.y); v1 = v1 > 0.f ? v1 : NEG * v1;
        float v2 = fmaf(eam, We4.z, xl4.z + xr4.z); v2 = v2 > 0.f ? v2 : NEG * v2;
        float v3 = fmaf(eam, We4.w, xl4.w + xr4.w); v3 = v3 > 0.f ? v3 : NEG * v3;
        float p = v0 * att4.x;
        p = fmaf(v1, att4.y, p);
        p = fmaf(v2, att4.z, p);
        p = fmaf(v3, att4.w, p);
        p += __shfl_xor_sync(0xffffffffu, p, 4);
        p += __shfl_xor_sync(0xffffffffu, p, 2);
        p += __shfl_xor_sync(0xffffffffu, p, 1);
        m = p;
    }
    float  s   = 1.f;
    float4 acc = xl4;

    const int e0 = g_indptr[node], e1 = g_indptr[node + 1];
    int e = e0;

    for (; e + 2 <= e1; e += 2) {
        int   s0 = g_csr_src[e],  s1 = g_csr_src[e + 1];
        float a0 = g_csr_ea[e],   a1 = g_csr_ea[e + 1];
        float4 x0 = h4_to_f4(__ldg((const uint2*)(g_xlh + (size_t)s0 * HIDN + base)));
        float4 x1 = h4_to_f4(__ldg((const uint2*)(g_xlh + (size_t)s1 * HIDN + base)));

        float v, q0, q1;
        v = fmaf(a0, We4.x, x0.x + xr4.x); v = v > 0.f ? v : NEG * v; q0 = v * att4.x;
        v = fmaf(a0, We4.y, x0.y + xr4.y); v = v > 0.f ? v : NEG * v; q0 = fmaf(v, att4.y, q0);
        v = fmaf(a0, We4.z, x0.z + xr4.z); v = v > 0.f ? v : NEG * v; q0 = fmaf(v, att4.z, q0);
        v = fmaf(a0, We4.w, x0.w + xr4.w); v = v > 0.f ? v : NEG * v; q0 = fmaf(v, att4.w, q0);
        v = fmaf(a1, We4.x, x1.x + xr4.x); v = v > 0.f ? v : NEG * v; q1 = v * att4.x;
        v = fmaf(a1, We4.y, x1.y + xr4.y); v = v > 0.f ? v : NEG * v; q1 = fmaf(v, att4.y, q1);
        v = fmaf(a1, We4.z, x1.z + xr4.z); v = v > 0.f ? v : NEG * v; q1 = fmaf(v, att4.z, q1);
        v = fmaf(a1, We4.w, x1.w + xr4.w); v = v > 0.f ? v : NEG * v; q1 = fmaf(v, att4.w, q1);

        q0 += __shfl_xor_sync(0xffffffffu, q0, 4);
        q1 += __shfl_xor_sync(0xffffffffu, q1, 4);
        q0 += __shfl_xor_sync(0xffffffffu, q0, 2);
        q1 += __shfl_xor_sync(0xffffffffu, q1, 2);
        q0 += __shfl_xor_sync(0xffffffffu, q0, 1);
        q1 += __shfl_xor_sync(0xffffffffu, q1, 1);

        float p0 = __expf(q0 - m);
        float p1 = __expf(q1 - m);
        s += p0 + p1;
        acc.x = fmaf(p0, x0.x, fmaf(p1, x1.x, acc.x));
        acc.y = fmaf(p0, x0.y, fmaf(p1, x1.y, acc.y));
        acc.z = fmaf(p0, x0.z, fmaf(p1, x1.z, acc.z));
        acc.w = fmaf(p0, x0.w, fmaf(p1, x1.w, acc.w));
    }
    if (e < e1) {
        int   s0 = g_csr_src[e];
        float a0 = g_csr_ea[e];
        float4 x0 = h4_to_f4(__ldg((const uint2*)(g_xlh + (size_t)s0 * HIDN + base)));
        float v, q0;
        v = fmaf(a0, We4.x, x0.x + xr4.x); v = v > 0.f ? v : NEG * v; q0 = v * att4.x;
        v = fmaf(a0, We4.y, x0.y + xr4.y); v = v > 0.f ? v : NEG * v; q0 = fmaf(v, att4.y, q0);
        v = fmaf(a0, We4.z, x0.z + xr4.z); v = v > 0.f ? v : NEG * v; q0 = fmaf(v, att4.z, q0);
        v = fmaf(a0, We4.w, x0.w + xr4.w); v = v > 0.f ? v : NEG * v; q0 = fmaf(v, att4.w, q0);
        q0 += __shfl_xor_sync(0xffffffffu, q0, 4);
        q0 += __shfl_xor_sync(0xffffffffu, q0, 2);
        q0 += __shfl_xor_sync(0xffffffffu, q0, 1);
        float p0 = __expf(q0 - m);
        s += p0;
        acc.x = fmaf(p0, x0.x, acc.x);
        acc.y = fmaf(p0, x0.y, acc.y);
        acc.z = fmaf(p0, x0.z, acc.z);
        acc.w = fmaf(p0, x0.w, acc.w);
    }

    const float inv = 1.f / s;
    const float4 gb4 = *(const float4*)(gb + base);
    float4 o;
    o.x = fmaxf(fmaf(acc.x, inv, gb4.x), 0.f) + h4.x;
    o.y = fmaxf(fmaf(acc.y, inv, gb4.y), 0.f) + h4.y;
    o.z = fmaxf(fmaf(acc.z, inv, gb4.z), 0.f) + h4.z;
    o.w = fmaxf(fmaf(acc.w, inv, gb4.w), 0.f) + h4.w;
    *(float4*)(g_h + (size_t)node * HIDN + base) = o;
}

// ---------------- pooling (h >= 0, so int-bit atomicMax is valid) ----------------
__global__ void k_pool() {
    int b = blockIdx.x >> 3;
    int chunk = blockIdx.x & 7;
    int j = threadIdx.x;
    int node0 = b * NPG + chunk * 128;
    float s = 0.f, mx = 0.f;
    #pragma unroll 4
    for (int t = 0; t < 128; t++) {
        float v = g_h[(size_t)(node0 + t) * HIDN + j];
        s += v;
        mx = fmaxf(mx, v);
    }
    atomicAdd(&g_pool_sum[b * HIDN + j], s);
    atomicMax((int*)&g_pool_max[b * HIDN + j], __float_as_int(mx));
}

// ---------------- fused action encoder + Q head ----------------
__global__ __launch_bounds__(256) void k_head(const float* __restrict__ at,
        const float* __restrict__ aW1, const float* __restrict__ ab1,
        const float* __restrict__ aW2, const float* __restrict__ ab2,
        const float* __restrict__ qW1, const float* __restrict__ qb1,
        const float* __restrict__ qW2, const float* __restrict__ qb2,
        const float* __restrict__ qW3, const float* __restrict__ qb3,
        float* __restrict__ out) {
    extern __shared__ float sm[];
    float* IN   = sm;                 // 16 x 516
    float* S1   = IN + 16 * 516;      // 16 x 128
    float* S2   = S1 + 16 * 128;      // 16 x 128
    float* tcol = S2 + 16 * 128;      // 128
    float* ps   = tcol + 128;         // 128
    float* pm   = ps + 128;           // 128

    const int tid = threadIdx.x;
    const int b   = blockIdx.x >> 1;
    const int a0  = (blockIdx.x & 1) * 16;

    if (tid < 128) {
        ps[tid] = g_pool_sum[b * HIDN + tid];
        pm[tid] = g_pool_max[b * HIDN + tid];
    }
    __syncthreads();

    for (int idx = tid; idx < 16 * 512; idx += 256) {
        int a = idx >> 9, q = idx & 511;
        int slot = q >> 7, col = q & 127;
        int node = (int)at[(size_t)(b * Ag + a0 + a) * 7 + slot] + b * NPG;
        IN[a * 516 + q] = g_h[(size_t)node * HIDN + col];
    }
    for (int idx = tid; idx < 16 * 3; idx += 256) {
        int a = idx / 3, ms = idx % 3;
        IN[a * 516 + 512 + ms] = at[(size_t)(b * Ag + a0 + a) * 7 + 4 + ms];
    }
    if (tid < 128) {
        float acc = qb1[tid];
        for (int k = 0; k < 128; k++) {
            float sv = ps[k];
            acc = fmaf(sv, qW1[k * 128 + tid], acc);
            acc = fmaf(sv * (1.f / 1024.f), qW1[(128 + k) * 128 + tid], acc);
            acc = fmaf(pm[k], qW1[(256 + k) * 128 + tid], acc);
        }
        tcol[tid] = acc;
    }
    __syncthreads();

    const int col = tid & 127;
    const int ab  = (tid >> 7) * 8;

    {
        float acc[8]; float bias = ab1[col];
        #pragma unroll
        for (int a = 0; a < 8; a++) acc[a] = bias;
        for (int k = 0; k < 515; k++) {
            float w = aW1[k * 128 + col];
            #pragma unroll
            for (int a = 0; a < 8; a++) acc[a] = fmaf(IN[(ab + a) * 516 + k], w, acc[a]);
        }
        #pragma unroll
        for (int a = 0; a < 8; a++) S1[(ab + a) * 128 + col] = fmaxf(acc[a], 0.f);
    }
    __syncthreads();
    {
        float acc[8]; float bias = ab2[col];
        #pragma unroll
        for (int a = 0; a < 8; a++) acc[a] = bias;
        for (int k = 0; k < 128; k++) {
            float w = aW2[k * 128 + col];
            #pragma unroll
            for (int a = 0; a < 8; a++) acc[a] = fmaf(S1[(ab + a) * 128 + k], w, acc[a]);
        }
        #pragma unroll
        for (int a = 0; a < 8; a++) S2[(ab + a) * 128 + col] = fmaxf(acc[a], 0.f);
    }
    __syncthreads();
    {
        float acc[8]; float t = tcol[col];
        #pragma unroll
        for (int a = 0; a < 8; a++) acc[a] = t;
        for (int k = 0; k < 128; k++) {
            float w = qW1[(384 + k) * 128 + col];
            #pragma unroll
            for (int a = 0; a < 8; a++) acc[a] = fmaf(S2[(ab + a) * 128 + k], w, acc[a]);
        }
        #pragma unroll
        for (int a = 0; a < 8; a++) S1[(ab + a) * 128 + col] = fmaxf(acc[a], 0.f);
    }
    __syncthreads();
    {
        float acc[8]; float bias = qb2[col];
        #pragma unroll
        for (int a = 0; a < 8; a++) acc[a] = bias;
        for (int k = 0; k < 128; k++) {
            float w = qW2[k * 128 + col];
            #pragma unroll
            for (int a = 0; a < 8; a++) acc[a] = fmaf(S1[(ab + a) * 128 + k], w, acc[a]);
        }
        #pragma unroll
        for (int a = 0; a < 8; a++) S2[(ab + a) * 128 + col] = fmaxf(acc[a], 0.f);
    }
    __syncthreads();
    {
        int w_id = tid >> 5, lane = tid & 31;
        for (int a = w_id; a < 16; a += 8) {
            float s = 0.f;
            #pragma unroll
            for (int kk = 0; kk < 4; kk++)
                s = fmaf(S2[a * 128 + kk * 32 + lane], qW3[kk * 32 + lane], s);
            #pragma unroll
            for (int o = 16; o > 0; o >>= 1) s += __shfl_xor_sync(0xffffffffu, s, o);
            if (lane == 0) out[b * Ag + a0 + a] = s + qb3[0];
        }
    }
}

// ---------------- launch ----------------
extern "C" void kernel_launch(void* const* d_in, const int* in_sizes, int n_in,
                              void* d_out, int out_size) {
    const float *x, *edge_attr, *action_tensor;
    const float *Wn, *bn, *gWl, *gbl, *gWr, *gbr, *gWe, *gatt, *gb;
    const float *aW1, *ab1, *aW2, *ab2, *qW1, *qb1, *qW2, *qb2, *qW3, *qb3;
    const int* edge_index;

    x             = (const float*)d_in[0];
    edge_attr     = (const float*)d_in[1];
    action_tensor = (const float*)d_in[2];

    if (in_sizes[3] > 100000) {
        edge_index = (const int*)d_in[3];
        Wn  = (const float*)d_in[6];  bn  = (const float*)d_in[7];
        gWl = (const float*)d_in[8];  gWr = (const float*)d_in[9];
        gWe = (const float*)d_in[10]; gatt= (const float*)d_in[11];
        gbl = (const float*)d_in[12]; gbr = (const float*)d_in[13];
        gb  = (const float*)d_in[14];
        aW1 = (const float*)d_in[15]; ab1 = (const float*)d_in[16];
        aW2 = (const float*)d_in[17]; ab2 = (const float*)d_in[18];
        qW1 = (const float*)d_in[19]; qb1 = (const float*)d_in[20];
        qW2 = (const float*)d_in[21]; qb2 = (const float*)d_in[22];
        qW3 = (const float*)d_in[23]; qb3 = (const float*)d_in[24];
    } else {
        Wn  = (const float*)d_in[3];  bn  = (const float*)d_in[4];
        gWl = (const float*)d_in[5];  gbl = (const float*)d_in[6];
        gWr = (const float*)d_in[7];  gbr = (const float*)d_in[8];
        gWe = (const float*)d_in[9];  gatt= (const float*)d_in[10];
        gb  = (const float*)d_in[11];
        aW1 = (const float*)d_in[12]; ab1 = (const float*)d_in[13];
        aW2 = (const float*)d_in[14]; ab2 = (const float*)d_in[15];
        qW1 = (const float*)d_in[16]; qb1 = (const float*)d_in[17];
        qW2 = (const float*)d_in[18]; qb2 = (const float*)d_in[19];
        qW3 = (const float*)d_in[20]; qb3 = (const float*)d_in[21];
        edge_index = (const int*)d_in[22];
    }

    const int SMEM_G = (128 * 132 + 128 * 256) * 4;                   // 198656
    const int SMEM_H = (16 * 516 + 2 * 16 * 128 + 3 * 128) * 4;       // 50944
    cudaFuncSetAttribute(k_gemm_dual, cudaFuncAttributeMaxDynamicSharedMemorySize, SMEM_G);
    cudaFuncSetAttribute(k_head,      cudaFuncAttributeMaxDynamicSharedMemorySize, SMEM_H);

    k_zero<<<Nn / 256, 256>>>();                                       // 1
    k_prep<<<Nn * 32 / 256, 256>>>(x, Wn, bn, edge_index, edge_attr);  // 2
    k_scan<<<1, 1024>>>();                                             // 3
    k_gemm_dual<<<Nn / 128, 512, SMEM_G>>>(gWl, gWr, gbl, gbr);        // 4 <- ncu capture target
    k_fill<<<Eg / 256, 256>>>(edge_index, edge_attr);                  // 5
    k_edge<<<Nn / 8, 256>>>(gWe, gatt, gb);                            // 6

    for (int l = 1; l < Lg; l++) {
        k_gemm_dual<<<Nn / 128, 512, SMEM_G>>>(gWl + l * HIDN * HIDN, gWr + l * HIDN * HIDN,
                                               gbl + l * HIDN, gbr + l * HIDN);
        k_edge<<<Nn / 8, 256>>>(gWe + l * HIDN, gatt + l * HIDN, gb + l * HIDN);
    }

    k_pool<<<Bg * 8, 128>>>();
    k_head<<<Bg * 2, 256, SMEM_H>>>(action_tensor, aW1, ab1, aW2, ab2,
                                    qW1, qb1, qW2, qb2, qW3, qb3, (float*)d_out);
}

// round 9
// speedup vs baseline: 1.7645x; 1.3178x over previous
#include <cuda_runtime.h>
#include <cuda_fp16.h>
#include <math.h>
#include <stdint.h>

#define Nn   65536
#define Bg   64
#define NPG  1024
#define Ag   32
#define HIDN 128
#define Eg   262144
#define Lg   3
#define NEG  0.2f

// ---------------- scratch (device globals; no allocation allowed) ----------------
__device__ float  g_h[Nn * HIDN];
__device__ __half g_xlh[Nn * HIDN];
__device__ __half g_xrh[Nn * HIDN];
__device__ __half g_w1h[HIDN * HIDN];   // W1^T fp16, row-major [n][k]
__device__ __half g_w2h[HIDN * HIDN];   // W2^T fp16, row-major [n][k]
__device__ int    g_indptr[Nn + 1];
__device__ int    g_cursor[Nn];
__device__ int    g_deg[Nn];
__device__ int    g_csr_src[Eg];
__device__ float  g_csr_ea[Eg];
__device__ float  g_partial[1024];
__device__ float  g_ea_mean;
__device__ float  g_pool_sum[Bg * HIDN];
__device__ float  g_pool_max[Bg * HIDN];

__device__ __forceinline__ float4 h4_to_f4(uint2 u) {
    __half2 a = *(__half2*)&u.x;
    __half2 b = *(__half2*)&u.y;
    float2 fa = __half22float2(a);
    float2 fb = __half22float2(b);
    return make_float4(fa.x, fa.y, fb.x, fb.y);
}

// ---------------- launch 1: zero counters ----------------
__global__ void k_zero() {
    int i = blockIdx.x * blockDim.x + threadIdx.x;
    if (i < Nn) g_deg[i] = 0;
    if (i < Bg * HIDN) { g_pool_sum[i] = 0.f; g_pool_max[i] = 0.f; }
}

// ---------------- launch 2: fused h0-init + degree histogram + edge_attr mean ----------------
__global__ void k_prep(const float* __restrict__ x, const float* __restrict__ Wn,
                       const float* __restrict__ bn,
                       const int* __restrict__ ei, const float* __restrict__ ea) {
    int idx = blockIdx.x * 256 + threadIdx.x;
    {
        int node = idx >> 5;
        int c = (idx & 31) << 2;
        float xv = x[node];
        float4 w = *(const float4*)(Wn + c);
        float4 b = *(const float4*)(bn + c);
        float4 o;
        o.x = fmaxf(fmaf(xv, w.x, b.x), 0.f);
        o.y = fmaxf(fmaf(xv, w.y, b.y), 0.f);
        o.z = fmaxf(fmaf(xv, w.z, b.z), 0.f);
        o.w = fmaxf(fmaf(xv, w.w, b.w), 0.f);
        *(float4*)(g_h + node * HIDN + c) = o;
    }
    if (blockIdx.x < Eg / 256) {
        __shared__ float red[256];
        atomicAdd(&g_deg[ei[Eg + idx]], 1);
        red[threadIdx.x] = ea[idx];
        __syncthreads();
        for (int st = 128; st > 0; st >>= 1) {
            if (threadIdx.x < st) red[threadIdx.x] += red[threadIdx.x + st];
            __syncthreads();
        }
        if (threadIdx.x == 0) g_partial[blockIdx.x] = red[0];
    }
}

// ---------------- W converter: W[k][n] -> WT[n][k] fp16 ----------------
__global__ void k_wconv(const float* __restrict__ W1, const float* __restrict__ W2) {
    int idx = blockIdx.x * 256 + threadIdx.x;   // 16384 threads
    int k = idx >> 7, n = idx & 127;
    g_w1h[n * HIDN + k] = __float2half(W1[idx]);
    g_w2h[n * HIDN + k] = __float2half(W2[idx]);
}

// ---------------- HMMA dual GEMM: xl = h@W1+b1, xr = h@W2+b2 (fp16 in, fp32 acc) ----------------
// CTA = 256 thr, tile 128 rows. smem: A[128][136], WT1[128][136], WT2[128][136] fp16.
// Warp w: rows 32*(w&3), cols 64*(w>>2); per matrix: 2 m-tiles x 8 n-tiles, 8 k-steps of k16.
#define SPITCH 136
__global__ __launch_bounds__(256) void k_gemm_mma(const float* __restrict__ b1,
                                                  const float* __restrict__ b2) {
    extern __shared__ __half smh[];
    __half* sA  = smh;                   // [128][136]
    __half* sB1 = sA  + 128 * SPITCH;
    __half* sB2 = sB1 + 128 * SPITCH;

    const int tid  = threadIdx.x;
    const int row0 = blockIdx.x * 128;

    // stage: thread = (row = tid>>1, 64-col half)
    {
        int row = tid >> 1, c0 = (tid & 1) * 64;
        const float*  srcA = g_h + (size_t)(row0 + row) * HIDN + c0;
        const __half* s1   = g_w1h + row * HIDN + c0;
        const __half* s2   = g_w2h + row * HIDN + c0;
        __half* dA = sA  + row * SPITCH + c0;
        __half* d1 = sB1 + row * SPITCH + c0;
        __half* d2 = sB2 + row * SPITCH + c0;
        #pragma unroll
        for (int j = 0; j < 64; j += 8) {
            float4 f0 = *(const float4*)(srcA + j);
            float4 f1 = *(const float4*)(srcA + j + 4);
            uint4 u;
            *(__half2*)&u.x = __floats2half2_rn(f0.x, f0.y);
            *(__half2*)&u.y = __floats2half2_rn(f0.z, f0.w);
            *(__half2*)&u.z = __floats2half2_rn(f1.x, f1.y);
            *(__half2*)&u.w = __floats2half2_rn(f1.z, f1.w);
            *(uint4*)(dA + j) = u;
            *(uint4*)(d1 + j) = *(const uint4*)(s1 + j);
            *(uint4*)(d2 + j) = *(const uint4*)(s2 + j);
        }
    }
    __syncthreads();

    const int warp = tid >> 5, lane = tid & 31;
    const int mrow = (warp & 3) * 32;     // output rows mrow..mrow+31
    const int ncol = (warp >> 2) * 64;    // output cols ncol..ncol+63

    uint32_t smem_u32;
    asm("{ .reg .u64 t; cvta.to.shared.u64 t, %1; cvt.u32.u64 %0, t; }"
        : "=r"(smem_u32) : "l"(smh));
    const uint32_t aBase  = smem_u32;
    const uint32_t b1Base = smem_u32 + 128 * SPITCH * 2;
    const uint32_t b2Base = b1Base + 128 * SPITCH * 2;

    // ldmatrix lane addressing
    const int l7   = lane & 7;
    const int rsel = ((lane >> 3) & 1) * 8;   // +8 rows for matrices 1,3
    const int csel = (lane >> 4) * 8;         // +8 cols for matrices 2,3
    // A tile (mrow + m*16, k0): addr = aBase + ((mrow + m*16 + l7 + rsel)*SPITCH + csel + k0)*2
    uint32_t aOff[2];
    #pragma unroll
    for (int m = 0; m < 2; m++)
        aOff[m] = aBase + (uint32_t)((mrow + m * 16 + l7 + rsel) * SPITCH + csel) * 2;
    // B n-pair np: rows = ncol + np*16 + l7 + csel(!), cols = k0 + rsel(!)
    // (B matrices: m0 rows n0..7/k-lo, m1 rows n0..7/k-hi, m2 rows n0+8/k-lo, m3 rows n0+8/k-hi)
    const int bRow = l7 + (lane >> 4) * 8;
    const int bCol = ((lane >> 3) & 1) * 8;
    uint32_t bOff[4];
    #pragma unroll
    for (int np = 0; np < 4; np++)
        bOff[np] = (uint32_t)((ncol + np * 16 + bRow) * SPITCH + bCol) * 2;

    #pragma unroll
    for (int mat = 0; mat < 2; mat++) {
        const uint32_t bBase = mat ? b2Base : b1Base;
        const float* bias    = mat ? b2 : b1;
        __half* dst          = mat ? g_xrh : g_xlh;

        float acc[2][8][4];
        #pragma unroll
        for (int m = 0; m < 2; m++)
            #pragma unroll
            for (int n = 0; n < 8; n++)
                #pragma unroll
                for (int q = 0; q < 4; q++) acc[m][n][q] = 0.f;

        #pragma unroll
        for (int k0 = 0; k0 < 128; k0 += 16) {
            uint32_t a[2][4];
            #pragma unroll
            for (int m = 0; m < 2; m++)
                asm volatile("ldmatrix.sync.aligned.m8n8.x4.shared.b16 {%0,%1,%2,%3}, [%4];"
                    : "=r"(a[m][0]), "=r"(a[m][1]), "=r"(a[m][2]), "=r"(a[m][3])
                    : "r"(aOff[m] + k0 * 2));
            uint32_t b[8][2];
            #pragma unroll
            for (int np = 0; np < 4; np++) {
                uint32_t r0, r1, r2, r3;
                asm volatile("ldmatrix.sync.aligned.m8n8.x4.shared.b16 {%0,%1,%2,%3}, [%4];"
                    : "=r"(r0), "=r"(r1), "=r"(r2), "=r"(r3)
                    : "r"(bBase + bOff[np] + k0 * 2));
                b[np * 2][0] = r0; b[np * 2][1] = r1;
                b[np * 2 + 1][0] = r2; b[np * 2 + 1][1] = r3;
            }
            #pragma unroll
            for (int m = 0; m < 2; m++)
                #pragma unroll
                for (int n = 0; n < 8; n++)
                    asm volatile(
                        "mma.sync.aligned.m16n8k16.row.col.f32.f16.f16.f32 "
                        "{%0,%1,%2,%3}, {%4,%5,%6,%7}, {%8,%9}, {%0,%1,%2,%3};"
                        : "+f"(acc[m][n][0]), "+f"(acc[m][n][1]),
                          "+f"(acc[m][n][2]), "+f"(acc[m][n][3])
                        : "r"(a[m][0]), "r"(a[m][1]), "r"(a[m][2]), "r"(a[m][3]),
                          "r"(b[n][0]), "r"(b[n][1]));
        }

        // epilogue: d0,d1 -> (row, col..col+1); d2,d3 -> (row+8, col..col+1)
        const int gid = lane >> 2, t4 = lane & 3;
        #pragma unroll
        for (int m = 0; m < 2; m++) {
            #pragma unroll
            for (int n = 0; n < 8; n++) {
                int col = ncol + n * 8 + t4 * 2;
                float bx = __ldg(&bias[col]), by = __ldg(&bias[col + 1]);
                int r0w = row0 + mrow + m * 16 + gid;
                *(__half2*)(dst + (size_t)r0w * HIDN + col) =
                    __floats2half2_rn(acc[m][n][0] + bx, acc[m][n][1] + by);
                *(__half2*)(dst + (size_t)(r0w + 8) * HIDN + col) =
                    __floats2half2_rn(acc[m][n][2] + bx, acc[m][n][3] + by);
            }
        }
    }
}

// ---------------- exclusive scan of degrees + finish edge_attr mean ----------------
__global__ __launch_bounds__(1024) void k_scan() {
    __shared__ int   ssum[1024];
    __shared__ float fred[1024];
    int t = threadIdx.x;

    fred[t] = g_partial[t];
    int base = t * 64;
    int s = 0;
    #pragma unroll 8
    for (int i = 0; i < 64; i++) s += g_deg[base + i];
    ssum[t] = s; __syncthreads();
    for (int off = 1; off < 1024; off <<= 1) {
        int v = (t >= off) ? ssum[t - off] : 0;
        __syncthreads();
        ssum[t] += v;
        __syncthreads();
    }
    int run = (t == 0) ? 0 : ssum[t - 1];
    for (int i = 0; i < 64; i++) {
        g_indptr[base + i] = run;
        g_cursor[base + i] = run;
        run += g_deg[base + i];
    }
    if (t == 1023) g_indptr[Nn] = run;

    for (int st = 512; st > 0; st >>= 1) {
        __syncthreads();
        if (t < st) fred[t] += fred[t + st];
    }
    __syncthreads();
    if (t == 0) g_ea_mean = fred[0] / (float)Eg;
}

// ---------------- CSR fill ----------------
__global__ void k_fill(const int* __restrict__ ei, const float* __restrict__ ea) {
    int e = blockIdx.x * blockDim.x + threadIdx.x;
    if (e < Eg) {
        int d = ei[Eg + e];
        int pos = atomicAdd(&g_cursor[d], 1);
        g_csr_src[pos] = ei[e];
        g_csr_ea[pos]  = ea[e];
    }
}

// ---------------- edge aggregation (fp16 gathers, fixed-offset softmax) ----------------
__global__ __launch_bounds__(256) void k_edge(const float* __restrict__ We,
                                              const float* __restrict__ att,
                                              const float* __restrict__ gb) {
    int node = (blockIdx.x * blockDim.x + threadIdx.x) >> 5;
    int lane = threadIdx.x & 31;
    if (node >= Nn) return;
    const int base = ((lane >> 3) << 5) + ((lane & 7) << 2);

    const float4 We4  = *(const float4*)(We + base);
    const float4 att4 = *(const float4*)(att + base);
    const float4 xr4  = h4_to_f4(*(const uint2*)(g_xrh + (size_t)node * HIDN + base));
    const float4 xl4  = h4_to_f4(*(const uint2*)(g_xlh + (size_t)node * HIDN + base));
    const float4 h4   = *(const float4*)(g_h + (size_t)node * HIDN + base);
    const float  eam  = g_ea_mean;

    float m;
    {
        float v0 = fmaf(eam, We4.x, xl4.x + xr4.x); v0 = v0 > 0.f ? v0 : NEG * v0;
        float v1 = fmaf(eam, We4.y, xl4.y + xr4.y); v1 = v1 > 0.f ? v1 : NEG * v1;
        float v2 = fmaf(eam, We4.z, xl4.z + xr4.z); v2 = v2 > 0.f ? v2 : NEG * v2;
        float v3 = fmaf(eam, We4.w, xl4.w + xr4.w); v3 = v3 > 0.f ? v3 : NEG * v3;
        float p = v0 * att4.x;
        p = fmaf(v1, att4.y, p);
        p = fmaf(v2, att4.z, p);
        p = fmaf(v3, att4.w, p);
        p += __shfl_xor_sync(0xffffffffu, p, 4);
        p += __shfl_xor_sync(0xffffffffu, p, 2);
        p += __shfl_xor_sync(0xffffffffu, p, 1);
        m = p;
    }
    float  s   = 1.f;
    float4 acc = xl4;

    const int e0 = g_indptr[node], e1 = g_indptr[node + 1];
    int e = e0;

    for (; e + 2 <= e1; e += 2) {
        int   s0 = g_csr_src[e],  s1 = g_csr_src[e + 1];
        float a0 = g_csr_ea[e],   a1 = g_csr_ea[e + 1];
        float4 x0 = h4_to_f4(__ldg((const uint2*)(g_xlh + (size_t)s0 * HIDN + base)));
        float4 x1 = h4_to_f4(__ldg((const uint2*)(g_xlh + (size_t)s1 * HIDN + base)));

        float v, q0, q1;
        v = fmaf(a0, We4.x, x0.x + xr4.x); v = v > 0.f ? v : NEG * v; q0 = v * att4.x;
        v = fmaf(a0, We4.y, x0.y + xr4.y); v = v > 0.f ? v : NEG * v; q0 = fmaf(v, att4.y, q0);
        v = fmaf(a0, We4.z, x0.z + xr4.z); v = v > 0.f ? v : NEG * v; q0 = fmaf(v, att4.z, q0);
        v = fmaf(a0, We4.w, x0.w + xr4.w); v = v > 0.f ? v : NEG * v; q0 = fmaf(v, att4.w, q0);
        v = fmaf(a1, We4.x, x1.x + xr4.x); v = v > 0.f ? v : NEG * v; q1 = v * att4.x;
        v = fmaf(a1, We4.y, x1.y + xr4.y); v = v > 0.f ? v : NEG * v; q1 = fmaf(v, att4.y, q1);
        v = fmaf(a1, We4.z, x1.z + xr4.z); v = v > 0.f ? v : NEG * v; q1 = fmaf(v, att4.z, q1);
        v = fmaf(a1, We4.w, x1.w + xr4.w); v = v > 0.f ? v : NEG * v; q1 = fmaf(v, att4.w, q1);

        q0 += __shfl_xor_sync(0xffffffffu, q0, 4);
        q1 += __shfl_xor_sync(0xffffffffu, q1, 4);
        q0 += __shfl_xor_sync(0xffffffffu, q0, 2);
        q1 += __shfl_xor_sync(0xffffffffu, q1, 2);
        q0 += __shfl_xor_sync(0xffffffffu, q0, 1);
        q1 += __shfl_xor_sync(0xffffffffu, q1, 1);

        float p0 = __expf(q0 - m);
        float p1 = __expf(q1 - m);
        s += p0 + p1;
        acc.x = fmaf(p0, x0.x, fmaf(p1, x1.x, acc.x));
        acc.y = fmaf(p0, x0.y, fmaf(p1, x1.y, acc.y));
        acc.z = fmaf(p0, x0.z, fmaf(p1, x1.z, acc.z));
        acc.w = fmaf(p0, x0.w, fmaf(p1, x1.w, acc.w));
    }
    if (e < e1) {
        int   s0 = g_csr_src[e];
        float a0 = g_csr_ea[e];
        float4 x0 = h4_to_f4(__ldg((const uint2*)(g_xlh + (size_t)s0 * HIDN + base)));
        float v, q0;
        v = fmaf(a0, We4.x, x0.x + xr4.x); v = v > 0.f ? v : NEG * v; q0 = v * att4.x;
        v = fmaf(a0, We4.y, x0.y + xr4.y); v = v > 0.f ? v : NEG * v; q0 = fmaf(v, att4.y, q0);
        v = fmaf(a0, We4.z, x0.z + xr4.z); v = v > 0.f ? v : NEG * v; q0 = fmaf(v, att4.z, q0);
        v = fmaf(a0, We4.w, x0.w + xr4.w); v = v > 0.f ? v : NEG * v; q0 = fmaf(v, att4.w, q0);
        q0 += __shfl_xor_sync(0xffffffffu, q0, 4);
        q0 += __shfl_xor_sync(0xffffffffu, q0, 2);
        q0 += __shfl_xor_sync(0xffffffffu, q0, 1);
        float p0 = __expf(q0 - m);
        s += p0;
        acc.x = fmaf(p0, x0.x, acc.x);
        acc.y = fmaf(p0, x0.y, acc.y);
        acc.z = fmaf(p0, x0.z, acc.z);
        acc.w = fmaf(p0, x0.w, acc.w);
    }

    const float inv = 1.f / s;
    const float4 gb4 = *(const float4*)(gb + base);
    float4 o;
    o.x = fmaxf(fmaf(acc.x, inv, gb4.x), 0.f) + h4.x;
    o.y = fmaxf(fmaf(acc.y, inv, gb4.y), 0.f) + h4.y;
    o.z = fmaxf(fmaf(acc.z, inv, gb4.z), 0.f) + h4.z;
    o.w = fmaxf(fmaf(acc.w, inv, gb4.w), 0.f) + h4.w;
    *(float4*)(g_h + (size_t)node * HIDN + base) = o;
}

// ---------------- pooling ----------------
__global__ void k_pool() {
    int b = blockIdx.x >> 3;
    int chunk = blockIdx.x & 7;
    int j = threadIdx.x;
    int node0 = b * NPG + chunk * 128;
    float s = 0.f, mx = 0.f;
    #pragma unroll 4
    for (int t = 0; t < 128; t++) {
        float v = g_h[(size_t)(node0 + t) * HIDN + j];
        s += v;
        mx = fmaxf(mx, v);
    }
    atomicAdd(&g_pool_sum[b * HIDN + j], s);
    atomicMax((int*)&g_pool_max[b * HIDN + j], __float_as_int(mx));
}

// ---------------- fused action encoder + Q head ----------------
__global__ __launch_bounds__(256) void k_head(const float* __restrict__ at,
        const float* __restrict__ aW1, const float* __restrict__ ab1,
        const float* __restrict__ aW2, const float* __restrict__ ab2,
        const float* __restrict__ qW1, const float* __restrict__ qb1,
        const float* __restrict__ qW2, const float* __restrict__ qb2,
        const float* __restrict__ qW3, const float* __restrict__ qb3,
        float* __restrict__ out) {
    extern __shared__ float sm[];
    float* IN   = sm;
    float* S1   = IN + 16 * 516;
    float* S2   = S1 + 16 * 128;
    float* tcol = S2 + 16 * 128;
    float* ps   = tcol + 128;
    float* pm   = ps + 128;

    const int tid = threadIdx.x;
    const int b   = blockIdx.x >> 1;
    const int a0  = (blockIdx.x & 1) * 16;

    if (tid < 128) {
        ps[tid] = g_pool_sum[b * HIDN + tid];
        pm[tid] = g_pool_max[b * HIDN + tid];
    }
    __syncthreads();

    for (int idx = tid; idx < 16 * 512; idx += 256) {
        int a = idx >> 9, q = idx & 511;
        int slot = q >> 7, col = q & 127;
        int node = (int)at[(size_t)(b * Ag + a0 + a) * 7 + slot] + b * NPG;
        IN[a * 516 + q] = g_h[(size_t)node * HIDN + col];
    }
    for (int idx = tid; idx < 16 * 3; idx += 256) {
        int a = idx / 3, ms = idx % 3;
        IN[a * 516 + 512 + ms] = at[(size_t)(b * Ag + a0 + a) * 7 + 4 + ms];
    }
    if (tid < 128) {
        float acc = qb1[tid];
        for (int k = 0; k < 128; k++) {
            float sv = ps[k];
            acc = fmaf(sv, qW1[k * 128 + tid], acc);
            acc = fmaf(sv * (1.f / 1024.f), qW1[(128 + k) * 128 + tid], acc);
            acc = fmaf(pm[k], qW1[(256 + k) * 128 + tid], acc);
        }
        tcol[tid] = acc;
    }
    __syncthreads();

    const int col = tid & 127;
    const int ab  = (tid >> 7) * 8;

    {
        float acc[8]; float bias = ab1[col];
        #pragma unroll
        for (int a = 0; a < 8; a++) acc[a] = bias;
        for (int k = 0; k < 515; k++) {
            float w = aW1[k * 128 + col];
            #pragma unroll
            for (int a = 0; a < 8; a++) acc[a] = fmaf(IN[(ab + a) * 516 + k], w, acc[a]);
        }
        #pragma unroll
        for (int a = 0; a < 8; a++) S1[(ab + a) * 128 + col] = fmaxf(acc[a], 0.f);
    }
    __syncthreads();
    {
        float acc[8]; float bias = ab2[col];
        #pragma unroll
        for (int a = 0; a < 8; a++) acc[a] = bias;
        for (int k = 0; k < 128; k++) {
            float w = aW2[k * 128 + col];
            #pragma unroll
            for (int a = 0; a < 8; a++) acc[a] = fmaf(S1[(ab + a) * 128 + k], w, acc[a]);
        }
        #pragma unroll
        for (int a = 0; a < 8; a++) S2[(ab + a) * 128 + col] = fmaxf(acc[a], 0.f);
    }
    __syncthreads();
    {
        float acc[8]; float t = tcol[col];
        #pragma unroll
        for (int a = 0; a < 8; a++) acc[a] = t;
        for (int k = 0; k < 128; k++) {
            float w = qW1[(384 + k) * 128 + col];
            #pragma unroll
            for (int a = 0; a < 8; a++) acc[a] = fmaf(S2[(ab + a) * 128 + k], w, acc[a]);
        }
        #pragma unroll
        for (int a = 0; a < 8; a++) S1[(ab + a) * 128 + col] = fmaxf(acc[a], 0.f);
    }
    __syncthreads();
    {
        float acc[8]; float bias = qb2[col];
        #pragma unroll
        for (int a = 0; a < 8; a++) acc[a] = bias;
        for (int k = 0; k < 128; k++) {
            float w = qW2[k * 128 + col];
            #pragma unroll
            for (int a = 0; a < 8; a++) acc[a] = fmaf(S1[(ab + a) * 128 + k], w, acc[a]);
        }
        #pragma unroll
        for (int a = 0; a < 8; a++) S2[(ab + a) * 128 + col] = fmaxf(acc[a], 0.f);
    }
    __syncthreads();
    {
        int w_id = tid >> 5, lane = tid & 31;
        for (int a = w_id; a < 16; a += 8) {
            float s = 0.f;
            #pragma unroll
            for (int kk = 0; kk < 4; kk++)
                s = fmaf(S2[a * 128 + kk * 32 + lane], qW3[kk * 32 + lane], s);
            #pragma unroll
            for (int o = 16; o > 0; o >>= 1) s += __shfl_xor_sync(0xffffffffu, s, o);
            if (lane == 0) out[b * Ag + a0 + a] = s + qb3[0];
        }
    }
}

// ---------------- launch ----------------
extern "C" void kernel_launch(void* const* d_in, const int* in_sizes, int n_in,
                              void* d_out, int out_size) {
    const float *x, *edge_attr, *action_tensor;
    const float *Wn, *bn, *gWl, *gbl, *gWr, *gbr, *gWe, *gatt, *gb;
    const float *aW1, *ab1, *aW2, *ab2, *qW1, *qb1, *qW2, *qb2, *qW3, *qb3;
    const int* edge_index;

    x             = (const float*)d_in[0];
    edge_attr     = (const float*)d_in[1];
    action_tensor = (const float*)d_in[2];

    if (in_sizes[3] > 100000) {
        edge_index = (const int*)d_in[3];
        Wn  = (const float*)d_in[6];  bn  = (const float*)d_in[7];
        gWl = (const float*)d_in[8];  gWr = (const float*)d_in[9];
        gWe = (const float*)d_in[10]; gatt= (const float*)d_in[11];
        gbl = (const float*)d_in[12]; gbr = (const float*)d_in[13];
        gb  = (const float*)d_in[14];
        aW1 = (const float*)d_in[15]; ab1 = (const float*)d_in[16];
        aW2 = (const float*)d_in[17]; ab2 = (const float*)d_in[18];
        qW1 = (const float*)d_in[19]; qb1 = (const float*)d_in[20];
        qW2 = (const float*)d_in[21]; qb2 = (const float*)d_in[22];
        qW3 = (const float*)d_in[23]; qb3 = (const float*)d_in[24];
    } else {
        Wn  = (const float*)d_in[3];  bn  = (const float*)d_in[4];
        gWl = (const float*)d_in[5];  gbl = (const float*)d_in[6];
        gWr = (const float*)d_in[7];  gbr = (const float*)d_in[8];
        gWe = (const float*)d_in[9];  gatt= (const float*)d_in[10];
        gb  = (const float*)d_in[11];
        aW1 = (const float*)d_in[12]; ab1 = (const float*)d_in[13];
        aW2 = (const float*)d_in[14]; ab2 = (const float*)d_in[15];
        qW1 = (const float*)d_in[16]; qb1 = (const float*)d_in[17];
        qW2 = (const float*)d_in[18]; qb2 = (const float*)d_in[19];
        qW3 = (const float*)d_in[20]; qb3 = (const float*)d_in[21];
        edge_index = (const int*)d_in[22];
    }

    const int SMEM_MMA = 3 * 128 * SPITCH * 2;                        // 104448
    const int SMEM_H   = (16 * 516 + 2 * 16 * 128 + 3 * 128) * 4;     // 50944
    cudaFuncSetAttribute(k_gemm_mma, cudaFuncAttributeMaxDynamicSharedMemorySize, SMEM_MMA);
    cudaFuncSetAttribute(k_head,     cudaFuncAttributeMaxDynamicSharedMemorySize, SMEM_H);

    k_zero<<<Nn / 256, 256>>>();                                       // 1
    k_prep<<<Nn * 32 / 256, 256>>>(x, Wn, bn, edge_index, edge_attr);  // 2
    k_wconv<<<64, 256>>>(gWl, gWr);                                    // 3
    k_gemm_mma<<<Nn / 128, 256, SMEM_MMA>>>(gbl, gbr);                 // 4 <- ncu capture target
    k_scan<<<1, 1024>>>();                                             // 5
    k_fill<<<Eg / 256, 256>>>(edge_index, edge_attr);                  // 6
    k_edge<<<Nn / 8, 256>>>(gWe, gatt, gb);                            // 7

    for (int l = 1; l < Lg; l++) {
        k_wconv<<<64, 256>>>(gWl + l * HIDN * HIDN, gWr + l * HIDN * HIDN);
        k_gemm_mma<<<Nn / 128, 256, SMEM_MMA>>>(gbl + l * HIDN, gbr + l * HIDN);
        k_edge<<<Nn / 8, 256>>>(gWe + l * HIDN, gatt + l * HIDN, gb + l * HIDN);
    }

    k_pool<<<Bg * 8, 128>>>();
    k_head<<<Bg * 2, 256, SMEM_H>>>(action_tensor, aW1, ab1, aW2, ab2,
                                    qW1, qb1, qW2, qb2, qW3, qb3, (float*)d_out);
}